// round 13
// baseline (speedup 1.0000x reference)
#include <cuda_runtime.h>
#include <cuda_bf16.h>
#include <cstdint>

// Problem constants
#define BB 4
#define SS 2048
#define DD 1024
#define HH 16
#define HDIM 64
#define MM (BB * SS)   // 8192

// ---------------------------------------------------------------------------
// Static device scratch (no runtime allocation allowed)
// ---------------------------------------------------------------------------
__device__ __nv_bfloat16 g_xh[MM * DD];
__device__ __nv_bfloat16 g_xl[MM * DD];
__device__ __nv_bfloat16 g_qh[MM * DD];
__device__ __nv_bfloat16 g_ql[MM * DD];
__device__ __nv_bfloat16 g_kh[MM * DD];
__device__ __nv_bfloat16 g_kl[MM * DD];
__device__ __nv_bfloat16 g_vth[DD * MM];       // V^T hi: [DD][MM]
__device__ __nv_bfloat16 g_vtl[DD * MM];       // V^T lo
__device__ __nv_bfloat16 g_ch[MM * DD];
__device__ __nv_bfloat16 g_cl[MM * DD];
__device__ __nv_bfloat16 g_wh[4][DD * DD];     // transposed W hi: [N][K]
__device__ __nv_bfloat16 g_wl[4][DD * DD];     // transposed W lo: [N][K]

// ---------------------------------------------------------------------------
// PTX helpers
// ---------------------------------------------------------------------------
__device__ __forceinline__ uint32_t smem_u32(const void* p) {
    return (uint32_t)__cvta_generic_to_shared(p);
}

__device__ __forceinline__ void cp16(uint32_t dst, const void* src) {
    asm volatile("cp.async.cg.shared.global [%0], [%1], 16;" :: "r"(dst), "l"(src));
}

__device__ __forceinline__ void ldsm4(uint32_t& r0, uint32_t& r1, uint32_t& r2,
                                      uint32_t& r3, uint32_t addr) {
    asm volatile("ldmatrix.sync.aligned.m8n8.x4.shared.b16 {%0,%1,%2,%3}, [%4];"
                 : "=r"(r0), "=r"(r1), "=r"(r2), "=r"(r3) : "r"(addr));
}

__device__ __forceinline__ void mma_bf16(float c[4], uint32_t a0, uint32_t a1,
                                         uint32_t a2, uint32_t a3,
                                         uint32_t b0, uint32_t b1) {
    asm volatile(
        "mma.sync.aligned.m16n8k16.row.col.f32.bf16.bf16.f32 "
        "{%0,%1,%2,%3}, {%4,%5,%6,%7}, {%8,%9}, {%0,%1,%2,%3};"
        : "+f"(c[0]), "+f"(c[1]), "+f"(c[2]), "+f"(c[3])
        : "r"(a0), "r"(a1), "r"(a2), "r"(a3), "r"(b0), "r"(b1));
}

// pack2(lo, hi): bf16x2, lo in bits[15:0], hi in bits[31:16]
__device__ __forceinline__ uint32_t pack2(float lo, float hi) {
    uint32_t r;
    asm("cvt.rn.bf16x2.f32 %0, %1, %2;" : "=r"(r) : "f"(hi), "f"(lo));
    return r;
}

// SW128 swizzle for 128B rows: row-relative byte offset of 16B segment sg (0..7)
__device__ __forceinline__ uint32_t swz(int row, int sg) {
    return (uint32_t)(row * 128 + (((sg ^ row) & 7) << 4));
}

// ---------------------------------------------------------------------------
// bf16-split HMMA GEMM, templated on output N-width BN (128 or 256).
//   BN=128: 256 threads, 2 CTA/SM (96KB smem)
//   BN=256: 512 threads, 1 CTA/SM (144KB smem) — 25% less L2 fill traffic
// 3-stage cp.async pipeline, K-chunks of 64, SW128-swizzled smem.
// OMODE: 0 = fp32 out, 1 = fp32 + bias, 2 = hi/lo bf16 split out,
//        3 = TRANSPOSED hi/lo bf16 split out (V^T [DD][MM], BN=128 only).
// ---------------------------------------------------------------------------
#define KC 64
#define OPBA 16384                   // A operand bytes per stage (128 x 128B)
#define NSTG 3
#define NCHUNK 48                    // 3 passes * (1024/64)

template <int OMODE, int BN>
__global__ __launch_bounds__((BN == 256) ? 512 : 256, (BN == 256) ? 1 : 2)
void gemm_mma(const __nv_bfloat16* __restrict__ Ah, const __nv_bfloat16* __restrict__ Al,
              const __nv_bfloat16* __restrict__ Bh, const __nv_bfloat16* __restrict__ Bl,
              const float* __restrict__ bias, float* __restrict__ C,
              __nv_bfloat16* __restrict__ Ch, __nv_bfloat16* __restrict__ Cl) {
    constexpr int THR = (BN == 256) ? 512 : 256;
    constexpr int STGB = OPBA + BN * 128;     // A + B bytes per stage

    extern __shared__ __align__(16) char dyn_smem[];
    const uint32_t smb = smem_u32(dyn_smem);

    const int tid = threadIdx.x;
    const int wid = tid >> 5;
    const int lane = tid & 31;
    const int wm = (wid & 3) * 32;
    const int wn = (wid >> 2) * 64;
    const int m0 = blockIdx.y * 128;
    const int n0 = blockIdx.x * BN;

    float acc[2][8][4];
#pragma unroll
    for (int i = 0; i < 2; i++)
#pragma unroll
        for (int j = 0; j < 8; j++)
#pragma unroll
            for (int t = 0; t < 4; t++) acc[i][j][t] = 0.f;

    auto load_chunk = [&](int c) {
        const int p = c >> 4;              // 0: Ah*Bh, 1: Ah*Bl, 2: Al*Bh
        const int koff = (c & 15) * KC;
        const __nv_bfloat16* Asrc = (p < 2) ? Ah : Al;
        const __nv_bfloat16* Bsrc = (p == 1) ? Bl : Bh;
        const uint32_t sa = smb + (c % NSTG) * STGB;
        const uint32_t sb = sa + OPBA;
#pragma unroll
        for (int i = 0; i < 1024 / THR; i++) {
            int seg = tid + THR * i;
            int row = seg >> 3, sg = seg & 7;
            cp16(sa + swz(row, sg), Asrc + (size_t)(m0 + row) * DD + koff + sg * 8);
        }
#pragma unroll
        for (int i = 0; i < BN * 8 / THR; i++) {
            int seg = tid + THR * i;
            int row = seg >> 3, sg = seg & 7;
            cp16(sb + swz(row, sg), Bsrc + (size_t)(n0 + row) * DD + koff + sg * 8);
        }
        asm volatile("cp.async.commit_group;" ::: "memory");
    };

    const int a_row = lane & 15;
    const int aseg = (lane >> 4);
    const int b_row = (lane & 7) + ((lane >> 4) << 3);
    const int bseg = (lane >> 3) & 1;

    load_chunk(0);
    load_chunk(1);

    for (int c = 0; c < NCHUNK; c++) {
        if (c + 2 < NCHUNK) {
            load_chunk(c + 2);
            asm volatile("cp.async.wait_group 2;" ::: "memory");
        } else if (c + 1 < NCHUNK) {
            asm volatile("cp.async.wait_group 1;" ::: "memory");
        } else {
            asm volatile("cp.async.wait_group 0;" ::: "memory");
        }
        __syncthreads();

        const uint32_t sa = smb + (c % NSTG) * STGB;
        const uint32_t sb = sa + OPBA;

#pragma unroll
        for (int ks = 0; ks < 4; ks++) {
            uint32_t a[2][4];
#pragma unroll
            for (int mt = 0; mt < 2; mt++) {
                const int r = wm + mt * 16 + a_row;
                ldsm4(a[mt][0], a[mt][1], a[mt][2], a[mt][3],
                      sa + swz(r, 2 * ks + aseg));
            }
            uint32_t b[8][2];
#pragma unroll
            for (int np = 0; np < 4; np++) {
                const int r = wn + np * 16 + b_row;
                ldsm4(b[2 * np][0], b[2 * np][1], b[2 * np + 1][0], b[2 * np + 1][1],
                      sb + swz(r, 2 * ks + bseg));
            }
#pragma unroll
            for (int mt = 0; mt < 2; mt++)
#pragma unroll
                for (int nt = 0; nt < 8; nt++)
                    mma_bf16(acc[mt][nt], a[mt][0], a[mt][1], a[mt][2], a[mt][3],
                             b[nt][0], b[nt][1]);
        }
        __syncthreads();
    }

    const int erow = lane >> 2;
    const int ecol = (lane & 3) * 2;

    if (OMODE == 3) {
        // Transposed split epilogue (BN=128 only): stage through smem
        // (64 n-rows x 128 m, pad 132), write V^T[n][m] hi/lo coalesced.
        float* sT = (float*)dyn_smem;
        const int srow = tid >> 2;
        const int scol = (tid & 3) * 32;
#pragma unroll
        for (int hf = 0; hf < 2; hf++) {
            __syncthreads();
            if ((wid >> 2) == hf) {
#pragma unroll
                for (int mt = 0; mt < 2; mt++) {
                    const int m = wm + mt * 16 + erow;
#pragma unroll
                    for (int nt = 0; nt < 8; nt++) {
                        const int nl = nt * 8 + ecol;
                        sT[(nl + 0) * 132 + m] = acc[mt][nt][0];
                        sT[(nl + 1) * 132 + m] = acc[mt][nt][1];
                        sT[(nl + 0) * 132 + m + 8] = acc[mt][nt][2];
                        sT[(nl + 1) * 132 + m + 8] = acc[mt][nt][3];
                    }
                }
            }
            __syncthreads();
            const size_t n_glob = n0 + hf * 64 + srow;
            const float* sp = sT + srow * 132 + scol;
            __nv_bfloat16* dh = Ch + n_glob * MM + m0 + scol;
            __nv_bfloat16* dl = Cl + n_glob * MM + m0 + scol;
#pragma unroll
            for (int j = 0; j < 32; j += 2) {
                float f0 = sp[j], f1 = sp[j + 1];
                float h0 = __bfloat162float(__float2bfloat16(f0));
                float h1 = __bfloat162float(__float2bfloat16(f1));
                *(uint32_t*)(dh + j) = pack2(f0, f1);
                *(uint32_t*)(dl + j) = pack2(f0 - h0, f1 - h1);
            }
        }
        return;
    }

#pragma unroll
    for (int mt = 0; mt < 2; mt++) {
        const int row = m0 + wm + mt * 16 + erow;
#pragma unroll
        for (int nt = 0; nt < 8; nt++) {
            const int col = n0 + wn + nt * 8 + ecol;
            float v0 = acc[mt][nt][0], v1 = acc[mt][nt][1];
            float v2 = acc[mt][nt][2], v3 = acc[mt][nt][3];
            if (OMODE == 1) {
                v0 += bias[col]; v1 += bias[col + 1];
                v2 += bias[col]; v3 += bias[col + 1];
            }
            if (OMODE == 2) {
                float h0 = __bfloat162float(__float2bfloat16(v0));
                float h1 = __bfloat162float(__float2bfloat16(v1));
                float h2 = __bfloat162float(__float2bfloat16(v2));
                float h3 = __bfloat162float(__float2bfloat16(v3));
                *(uint32_t*)&Ch[(size_t)row * DD + col] = pack2(v0, v1);
                *(uint32_t*)&Cl[(size_t)row * DD + col] = pack2(v0 - h0, v1 - h1);
                *(uint32_t*)&Ch[(size_t)(row + 8) * DD + col] = pack2(v2, v3);
                *(uint32_t*)&Cl[(size_t)(row + 8) * DD + col] = pack2(v2 - h2, v3 - h3);
            } else {
                float2 p0; p0.x = v0; p0.y = v1;
                float2 p1; p1.x = v2; p1.y = v3;
                *(float2*)&C[(size_t)row * DD + col] = p0;
                *(float2*)&C[(size_t)(row + 8) * DD + col] = p1;
            }
        }
    }
}

// ---------------------------------------------------------------------------
// Prep kernels
// ---------------------------------------------------------------------------
__global__ __launch_bounds__(256)
void cvt_split_kernel(const float* __restrict__ in, __nv_bfloat16* __restrict__ hi,
                      __nv_bfloat16* __restrict__ lo, int n4) {
    int i = blockIdx.x * blockDim.x + threadIdx.x;
    if (i >= n4) return;
    float4 v = ((const float4*)in)[i];
    float h0 = __bfloat162float(__float2bfloat16(v.x));
    float h1 = __bfloat162float(__float2bfloat16(v.y));
    float h2 = __bfloat162float(__float2bfloat16(v.z));
    float h3 = __bfloat162float(__float2bfloat16(v.w));
    ((uint32_t*)hi)[2 * i + 0] = pack2(v.x, v.y);
    ((uint32_t*)hi)[2 * i + 1] = pack2(v.z, v.w);
    ((uint32_t*)lo)[2 * i + 0] = pack2(v.x - h0, v.y - h1);
    ((uint32_t*)lo)[2 * i + 1] = pack2(v.z - h2, v.w - h3);
}

// All four W transpose+splits in one launch (z = which matrix).
__global__ __launch_bounds__(256)
void wsplit_t_all(const float* __restrict__ W0, const float* __restrict__ W1,
                  const float* __restrict__ W2, const float* __restrict__ W3,
                  __nv_bfloat16* __restrict__ Th, __nv_bfloat16* __restrict__ Tl) {
    __shared__ float t[32][33];
    const int z = blockIdx.z;
    const float* W = (z == 0) ? W0 : (z == 1) ? W1 : (z == 2) ? W2 : W3;
    __nv_bfloat16* th = Th + (size_t)z * DD * DD;
    __nv_bfloat16* tl = Tl + (size_t)z * DD * DD;
    const int bx = blockIdx.x * 32;
    const int by = blockIdx.y * 32;
    const int x = bx + threadIdx.x;
#pragma unroll
    for (int j = threadIdx.y; j < 32; j += 8)
        t[j][threadIdx.x] = W[(size_t)(by + j) * DD + x];
    __syncthreads();
    const int xo = by + threadIdx.x;
#pragma unroll
    for (int j = threadIdx.y; j < 32; j += 8) {
        float v = t[threadIdx.x][j];
        __nv_bfloat16 h = __float2bfloat16(v);
        th[(size_t)(bx + j) * DD + xo] = h;
        tl[(size_t)(bx + j) * DD + xo] = __float2bfloat16(v - __bfloat162float(h));
    }
}

// ---------------------------------------------------------------------------
// HMMA flash-attention, bf16 split precision, SW128 smem, 2 CTA/SM.
// qt reversed (heavy blocks launch first -> smaller scheduling tail).
// ---------------------------------------------------------------------------
#define QTB 16384                     // Q tile bytes (128 x 128B)
#define KVTB 8192                     // K/V tile bytes (64 x 128B)
#define KVSTGB (4 * KVTB)             // 32768 per stage
#define ATTN_SMEM_B (2 * QTB + 2 * KVSTGB)   // 98304 B

__global__ __launch_bounds__(256, 2)
void attn_mma(const __nv_bfloat16* __restrict__ qh, const __nv_bfloat16* __restrict__ ql,
              const __nv_bfloat16* __restrict__ kh, const __nv_bfloat16* __restrict__ kl,
              const __nv_bfloat16* __restrict__ vth, const __nv_bfloat16* __restrict__ vtl,
              __nv_bfloat16* __restrict__ ch, __nv_bfloat16* __restrict__ cl) {
    extern __shared__ __align__(16) char attn_smem[];
    const uint32_t smb = smem_u32(attn_smem);

    const int tid = threadIdx.x;
    const int wid = tid >> 5;
    const int lane = tid & 31;
    const int qt = (SS / 128 - 1) - blockIdx.x;   // heavy blocks first
    const int h = blockIdx.y;
    const int b = blockIdx.z;
    const int q0 = qt * 128;
    const int wm = wid * 16;
    const int g = lane >> 2;
    const int t_ = lane & 3;

    const size_t rowQ = (size_t)b * SS + q0;

    const int a_row = lane & 15;
    const int aseg = (lane >> 4);
    const int b_row = (lane & 7) + ((lane >> 4) << 3);
    const int bseg = (lane >> 3) & 1;

    // ---- load Q (hi+lo): 2048 segs of 16B, 8 per thread ----
#pragma unroll
    for (int i = 0; i < 8; i++) {
        int gi = tid + 256 * i;
        int tile = gi >> 10;            // 0=Qh, 1=Ql
        int gg = gi & 1023;
        int row = gg >> 3, sg = gg & 7;
        const __nv_bfloat16* src = (tile ? ql : qh) + (rowQ + row) * DD + h * HDIM + sg * 8;
        cp16(smb + tile * QTB + swz(row, sg), src);
    }

    auto load_kv = [&](int t, int s) {
        const size_t rowK = (size_t)b * SS + t * 64;
        const uint32_t base = smb + 2 * QTB + s * KVSTGB;
#pragma unroll
        for (int i = 0; i < 8; i++) {
            int gi = tid + 256 * i;
            int tile = gi >> 9;         // 0=Kh 1=Kl 2=Vth 3=Vtl
            int gg = gi & 511;
            int row = gg >> 3, sg = gg & 7;
            const __nv_bfloat16* src;
            if (tile == 0)      src = kh + (rowK + row) * DD + h * HDIM + sg * 8;
            else if (tile == 1) src = kl + (rowK + row) * DD + h * HDIM + sg * 8;
            else if (tile == 2) src = vth + (size_t)(h * HDIM + row) * MM + rowK + sg * 8;
            else                src = vtl + (size_t)(h * HDIM + row) * MM + rowK + sg * 8;
            cp16(base + tile * KVTB + swz(row, sg), src);
        }
        asm volatile("cp.async.commit_group;" ::: "memory");
    };

    const int ktiles = min(2 * qt + 3, SS / 64);

    load_kv(0, 0);

    float oacc[8][4];
    float m0 = -1e30f, m1 = -1e30f, l0 = 0.f, l1 = 0.f;
#pragma unroll
    for (int nt = 0; nt < 8; nt++)
#pragma unroll
        for (int e = 0; e < 4; e++) oacc[nt][e] = 0.f;

    for (int t = 0; t < ktiles; t++) {
        if (t + 1 < ktiles) {
            load_kv(t + 1, (t + 1) & 1);
            asm volatile("cp.async.wait_group 1;" ::: "memory");
        } else {
            asm volatile("cp.async.wait_group 0;" ::: "memory");
        }
        __syncthreads();

        const int s = t & 1;
        const int k0 = t * 64;
        // Pure-lookahead tile: only warp 7 (query row q0+127) has unmasked work.
        const bool skip = (k0 > q0 + 127) && (wid != 7);

        if (!skip) {
            const uint32_t sQh = smb;
            const uint32_t sQl = smb + QTB;
            const uint32_t sKh = smb + 2 * QTB + s * KVSTGB;
            const uint32_t sKl = sKh + KVTB;
            const uint32_t sVh = sKh + 2 * KVTB;
            const uint32_t sVl = sKh + 3 * KVTB;

            float sacc[8][4];
#pragma unroll
            for (int nt = 0; nt < 8; nt++)
#pragma unroll
                for (int e = 0; e < 4; e++) sacc[nt][e] = 0.f;

#pragma unroll
            for (int pass = 0; pass < 3; pass++) {
                const uint32_t A = (pass < 2) ? sQh : sQl;
                const uint32_t Bk = (pass == 1) ? sKl : sKh;
#pragma unroll
                for (int ks = 0; ks < 4; ks++) {
                    uint32_t a0, a1, a2, a3;
                    ldsm4(a0, a1, a2, a3, A + swz(wm + a_row, 2 * ks + aseg));
#pragma unroll
                    for (int np = 0; np < 4; np++) {
                        uint32_t b0, b1, b2, b3;
                        ldsm4(b0, b1, b2, b3, Bk + swz(np * 16 + b_row, 2 * ks + bseg));
                        mma_bf16(sacc[2 * np], a0, a1, a2, a3, b0, b1);
                        mma_bf16(sacc[2 * np + 1], a0, a1, a2, a3, b2, b3);
                    }
                }
            }

#pragma unroll
            for (int nt = 0; nt < 8; nt++)
#pragma unroll
                for (int e = 0; e < 4; e++) sacc[nt][e] *= 0.125f;

            const int qr0 = q0 + wm + g;
            if (k0 >= q0) {
#pragma unroll
                for (int nt = 0; nt < 8; nt++) {
                    const int c = k0 + nt * 8 + 2 * t_;
                    if (c     > qr0 + 1) sacc[nt][0] = -1e30f;
                    if (c + 1 > qr0 + 1) sacc[nt][1] = -1e30f;
                    if (c     > qr0 + 9) sacc[nt][2] = -1e30f;
                    if (c + 1 > qr0 + 9) sacc[nt][3] = -1e30f;
                }
            }

            float mx0 = -1e30f, mx1 = -1e30f;
#pragma unroll
            for (int nt = 0; nt < 8; nt++) {
                mx0 = fmaxf(mx0, fmaxf(sacc[nt][0], sacc[nt][1]));
                mx1 = fmaxf(mx1, fmaxf(sacc[nt][2], sacc[nt][3]));
            }
            mx0 = fmaxf(mx0, __shfl_xor_sync(0xffffffffu, mx0, 1));
            mx0 = fmaxf(mx0, __shfl_xor_sync(0xffffffffu, mx0, 2));
            mx1 = fmaxf(mx1, __shfl_xor_sync(0xffffffffu, mx1, 1));
            mx1 = fmaxf(mx1, __shfl_xor_sync(0xffffffffu, mx1, 2));

            const float mn0 = fmaxf(m0, mx0), mn1 = fmaxf(m1, mx1);
            const float cor0 = __expf(m0 - mn0), cor1 = __expf(m1 - mn1);
            m0 = mn0; m1 = mn1;

            float rs0 = 0.f, rs1 = 0.f;
#pragma unroll
            for (int nt = 0; nt < 8; nt++) {
                sacc[nt][0] = __expf(sacc[nt][0] - mn0); rs0 += sacc[nt][0];
                sacc[nt][1] = __expf(sacc[nt][1] - mn0); rs0 += sacc[nt][1];
                sacc[nt][2] = __expf(sacc[nt][2] - mn1); rs1 += sacc[nt][2];
                sacc[nt][3] = __expf(sacc[nt][3] - mn1); rs1 += sacc[nt][3];
            }
            rs0 += __shfl_xor_sync(0xffffffffu, rs0, 1);
            rs0 += __shfl_xor_sync(0xffffffffu, rs0, 2);
            rs1 += __shfl_xor_sync(0xffffffffu, rs1, 1);
            rs1 += __shfl_xor_sync(0xffffffffu, rs1, 2);
            l0 = l0 * cor0 + rs0;
            l1 = l1 * cor1 + rs1;

#pragma unroll
            for (int nt = 0; nt < 8; nt++) {
                oacc[nt][0] *= cor0; oacc[nt][1] *= cor0;
                oacc[nt][2] *= cor1; oacc[nt][3] *= cor1;
            }

#pragma unroll
            for (int ks = 0; ks < 4; ks++) {
                const float* P0 = sacc[2 * ks];
                const float* P1 = sacc[2 * ks + 1];
                float h00 = __bfloat162float(__float2bfloat16(P0[0]));
                float h01 = __bfloat162float(__float2bfloat16(P0[1]));
                float h02 = __bfloat162float(__float2bfloat16(P0[2]));
                float h03 = __bfloat162float(__float2bfloat16(P0[3]));
                float h10 = __bfloat162float(__float2bfloat16(P1[0]));
                float h11 = __bfloat162float(__float2bfloat16(P1[1]));
                float h12 = __bfloat162float(__float2bfloat16(P1[2]));
                float h13 = __bfloat162float(__float2bfloat16(P1[3]));
                uint32_t ah0 = pack2(P0[0], P0[1]);
                uint32_t ah1 = pack2(P0[2], P0[3]);
                uint32_t ah2 = pack2(P1[0], P1[1]);
                uint32_t ah3 = pack2(P1[2], P1[3]);
                uint32_t al0 = pack2(P0[0] - h00, P0[1] - h01);
                uint32_t al1 = pack2(P0[2] - h02, P0[3] - h03);
                uint32_t al2 = pack2(P1[0] - h10, P1[1] - h11);
                uint32_t al3 = pack2(P1[2] - h12, P1[3] - h13);

#pragma unroll
                for (int np = 0; np < 4; np++) {
                    uint32_t bh0, bh1, bh2, bh3, bl0, bl1, bl2, bl3;
                    ldsm4(bh0, bh1, bh2, bh3, sVh + swz(np * 16 + b_row, 2 * ks + bseg));
                    ldsm4(bl0, bl1, bl2, bl3, sVl + swz(np * 16 + b_row, 2 * ks + bseg));
                    mma_bf16(oacc[2 * np],     ah0, ah1, ah2, ah3, bh0, bh1);
                    mma_bf16(oacc[2 * np + 1], ah0, ah1, ah2, ah3, bh2, bh3);
                    mma_bf16(oacc[2 * np],     ah0, ah1, ah2, ah3, bl0, bl1);
                    mma_bf16(oacc[2 * np + 1], ah0, ah1, ah2, ah3, bl2, bl3);
                    mma_bf16(oacc[2 * np],     al0, al1, al2, al3, bh0, bh1);
                    mma_bf16(oacc[2 * np + 1], al0, al1, al2, al3, bh2, bh3);
                }
            }
        }
        __syncthreads();
    }

    const float il0 = 1.0f / l0, il1 = 1.0f / l1;
    const size_t r0g = (size_t)b * SS + q0 + wm + g;
    const size_t r1g = r0g + 8;
#pragma unroll
    for (int nt = 0; nt < 8; nt++) {
        const int col = h * HDIM + nt * 8 + 2 * t_;
        float f0 = oacc[nt][0] * il0, f1 = oacc[nt][1] * il0;
        float f2 = oacc[nt][2] * il1, f3 = oacc[nt][3] * il1;
        float e0 = __bfloat162float(__float2bfloat16(f0));
        float e1 = __bfloat162float(__float2bfloat16(f1));
        float e2 = __bfloat162float(__float2bfloat16(f2));
        float e3 = __bfloat162float(__float2bfloat16(f3));
        *(uint32_t*)&ch[r0g * DD + col] = pack2(f0, f1);
        *(uint32_t*)&cl[r0g * DD + col] = pack2(f0 - e0, f1 - e1);
        *(uint32_t*)&ch[r1g * DD + col] = pack2(f2, f3);
        *(uint32_t*)&cl[r1g * DD + col] = pack2(f2 - e2, f3 - e3);
    }
}

// ---------------------------------------------------------------------------
// kernel_launch
// ---------------------------------------------------------------------------
#define GEMM_SMEM_128 (NSTG * (OPBA + 128 * 128))   // 98304
#define GEMM_SMEM_256 (NSTG * (OPBA + 256 * 128))   // 147456

extern "C" void kernel_launch(void* const* d_in, const int* in_sizes, int n_in,
                              void* d_out, int out_size) {
    (void)in_sizes; (void)n_in; (void)out_size;
    const float* x  = (const float*)d_in[0];
    const float* Wq = (const float*)d_in[1];
    const float* Wk = (const float*)d_in[2];
    const float* Wv = (const float*)d_in[3];
    const float* Wo = (const float*)d_in[4];
    const float* bo = (const float*)d_in[5];
    float* out = (float*)d_out;

    __nv_bfloat16 *xh, *xl, *qh, *ql, *kh, *kl, *vth, *vtl, *ch, *cl, *wh, *wl;
    cudaGetSymbolAddress((void**)&xh, g_xh);
    cudaGetSymbolAddress((void**)&xl, g_xl);
    cudaGetSymbolAddress((void**)&qh, g_qh);
    cudaGetSymbolAddress((void**)&ql, g_ql);
    cudaGetSymbolAddress((void**)&kh, g_kh);
    cudaGetSymbolAddress((void**)&kl, g_kl);
    cudaGetSymbolAddress((void**)&vth, g_vth);
    cudaGetSymbolAddress((void**)&vtl, g_vtl);
    cudaGetSymbolAddress((void**)&ch, g_ch);
    cudaGetSymbolAddress((void**)&cl, g_cl);
    cudaGetSymbolAddress((void**)&wh, g_wh);
    cudaGetSymbolAddress((void**)&wl, g_wl);

    cudaFuncSetAttribute(attn_mma, cudaFuncAttributeMaxDynamicSharedMemorySize, ATTN_SMEM_B);
    cudaFuncSetAttribute(gemm_mma<1, 256>, cudaFuncAttributeMaxDynamicSharedMemorySize, GEMM_SMEM_256);
    cudaFuncSetAttribute(gemm_mma<2, 256>, cudaFuncAttributeMaxDynamicSharedMemorySize, GEMM_SMEM_256);
    cudaFuncSetAttribute(gemm_mma<3, 128>, cudaFuncAttributeMaxDynamicSharedMemorySize, GEMM_SMEM_128);

    // Prep
    const int n4 = MM * DD / 4;
    cvt_split_kernel<<<(n4 + 255) / 256, 256>>>(x, xh, xl, n4);
    dim3 tgrid(DD / 32, DD / 32, 4), tblk(32, 8);
    wsplit_t_all<<<tgrid, tblk>>>(Wq, Wk, Wv, Wo, wh, wl);

    // Projections (Q,K wide tiles -> split bf16; V -> transposed split, fused)
    dim3 ggridW(DD / 256, MM / 128);   // (4, 64)
    dim3 ggridN(DD / 128, MM / 128);   // (8, 64)
    gemm_mma<2, 256><<<ggridW, 512, GEMM_SMEM_256>>>(xh, xl, wh + 0 * DD * DD, wl + 0 * DD * DD,
                                                     nullptr, nullptr, qh, ql);
    gemm_mma<2, 256><<<ggridW, 512, GEMM_SMEM_256>>>(xh, xl, wh + 1 * DD * DD, wl + 1 * DD * DD,
                                                     nullptr, nullptr, kh, kl);
    gemm_mma<3, 128><<<ggridN, 256, GEMM_SMEM_128>>>(xh, xl, wh + 2 * DD * DD, wl + 2 * DD * DD,
                                                     nullptr, nullptr, vth, vtl);

    // Attention (HMMA split, qt reversed)
    dim3 agrid(SS / 128, HH, BB);
    attn_mma<<<agrid, 256, ATTN_SMEM_B>>>(qh, ql, kh, kl, vth, vtl, ch, cl);

    // Output projection (+bias)
    gemm_mma<1, 256><<<ggridW, 512, GEMM_SMEM_256>>>(ch, cl, wh + 3 * DD * DD, wl + 3 * DD * DD,
                                                     bo, out, nullptr, nullptr);
}

// round 14
// speedup vs baseline: 1.1952x; 1.1952x over previous
#include <cuda_runtime.h>
#include <cuda_bf16.h>
#include <cuda_fp16.h>
#include <cstdint>

// Problem constants
#define BB 4
#define SS 2048
#define DD 1024
#define HH 16
#define HDIM 64
#define MM (BB * SS)   // 8192

// ---------------------------------------------------------------------------
// Static device scratch
// ---------------------------------------------------------------------------
__device__ __nv_bfloat16 g_xh[MM * DD];
__device__ __nv_bfloat16 g_xl[MM * DD];
__device__ __half g_qh[MM * DD];
__device__ __half g_ql[MM * DD];
__device__ __half g_kh[MM * DD];               // K hi only (fp16 2-pass QK)
__device__ __half g_vth[DD * MM];              // V^T hi: [DD][MM]
__device__ __half g_vtl[DD * MM];              // V^T lo
__device__ __nv_bfloat16 g_ch[MM * DD];
__device__ __nv_bfloat16 g_cl[MM * DD];
__device__ __nv_bfloat16 g_wh[4][DD * DD];     // transposed W hi: [N][K]
__device__ __nv_bfloat16 g_wl[4][DD * DD];     // transposed W lo: [N][K]

// ---------------------------------------------------------------------------
// PTX helpers
// ---------------------------------------------------------------------------
__device__ __forceinline__ uint32_t smem_u32(const void* p) {
    return (uint32_t)__cvta_generic_to_shared(p);
}

__device__ __forceinline__ void cp16(uint32_t dst, const void* src) {
    asm volatile("cp.async.cg.shared.global [%0], [%1], 16;" :: "r"(dst), "l"(src));
}

__device__ __forceinline__ void ldsm4(uint32_t& r0, uint32_t& r1, uint32_t& r2,
                                      uint32_t& r3, uint32_t addr) {
    asm volatile("ldmatrix.sync.aligned.m8n8.x4.shared.b16 {%0,%1,%2,%3}, [%4];"
                 : "=r"(r0), "=r"(r1), "=r"(r2), "=r"(r3) : "r"(addr));
}

__device__ __forceinline__ void mma_bf16(float c[4], uint32_t a0, uint32_t a1,
                                         uint32_t a2, uint32_t a3,
                                         uint32_t b0, uint32_t b1) {
    asm volatile(
        "mma.sync.aligned.m16n8k16.row.col.f32.bf16.bf16.f32 "
        "{%0,%1,%2,%3}, {%4,%5,%6,%7}, {%8,%9}, {%0,%1,%2,%3};"
        : "+f"(c[0]), "+f"(c[1]), "+f"(c[2]), "+f"(c[3])
        : "r"(a0), "r"(a1), "r"(a2), "r"(a3), "r"(b0), "r"(b1));
}

__device__ __forceinline__ void mma_f16(float c[4], uint32_t a0, uint32_t a1,
                                        uint32_t a2, uint32_t a3,
                                        uint32_t b0, uint32_t b1) {
    asm volatile(
        "mma.sync.aligned.m16n8k16.row.col.f32.f16.f16.f32 "
        "{%0,%1,%2,%3}, {%4,%5,%6,%7}, {%8,%9}, {%0,%1,%2,%3};"
        : "+f"(c[0]), "+f"(c[1]), "+f"(c[2]), "+f"(c[3])
        : "r"(a0), "r"(a1), "r"(a2), "r"(a3), "r"(b0), "r"(b1));
}

// pack2(lo, hi): bf16x2, lo in bits[15:0]
__device__ __forceinline__ uint32_t pack2(float lo, float hi) {
    uint32_t r;
    asm("cvt.rn.bf16x2.f32 %0, %1, %2;" : "=r"(r) : "f"(hi), "f"(lo));
    return r;
}
// fp16x2 version
__device__ __forceinline__ uint32_t pack2h(float lo, float hi) {
    uint32_t r;
    asm("cvt.rn.f16x2.f32 %0, %1, %2;" : "=r"(r) : "f"(hi), "f"(lo));
    return r;
}

// SW128 swizzle for 128B rows
__device__ __forceinline__ uint32_t swz(int row, int sg) {
    return (uint32_t)(row * 128 + (((sg ^ row) & 7) << 4));
}

// ---------------------------------------------------------------------------
// bf16-split HMMA GEMM: 128x128 tile, 8 warps, 3-stage pipeline, KC=64,
// SW128 smem, SINGLE barrier per iteration.
// OMODE: 1 = fp32 + bias,
//        2 = fp16 hi/lo split out (Q),
//        3 = TRANSPOSED fp16 hi/lo split out (V^T [DD][MM]),
//        4 = fp16 hi only (K).
// ---------------------------------------------------------------------------
#define KC 64
#define OPB 16384
#define STGB (2 * OPB)
#define NSTG 3
#define NCHUNK 48
#define GEMM_SMEM (NSTG * STGB)      // 98304

template <int OMODE>
__global__ __launch_bounds__(256, 2)
void gemm_mma(const __nv_bfloat16* __restrict__ Ah, const __nv_bfloat16* __restrict__ Al,
              const __nv_bfloat16* __restrict__ Bh, const __nv_bfloat16* __restrict__ Bl,
              const float* __restrict__ bias, float* __restrict__ C,
              __half* __restrict__ Hh, __half* __restrict__ Hl) {
    extern __shared__ __align__(16) char dyn_smem[];
    const uint32_t smb = smem_u32(dyn_smem);

    const int tid = threadIdx.x;
    const int wid = tid >> 5;
    const int lane = tid & 31;
    const int wm = (wid & 3) * 32;
    const int wn = (wid >> 2) * 64;
    const int m0 = blockIdx.y * 128;
    const int n0 = blockIdx.x * 128;

    float acc[2][8][4];
#pragma unroll
    for (int i = 0; i < 2; i++)
#pragma unroll
        for (int j = 0; j < 8; j++)
#pragma unroll
            for (int t = 0; t < 4; t++) acc[i][j][t] = 0.f;

    int rowS[4], sgI[4];
#pragma unroll
    for (int i = 0; i < 4; i++) {
        int seg = tid + 256 * i;
        rowS[i] = seg >> 3;
        sgI[i] = seg & 7;
    }

    auto load_chunk = [&](int c) {
        const int p = c >> 4;
        const int koff = (c & 15) * KC;
        const __nv_bfloat16* Asrc = (p < 2) ? Ah : Al;
        const __nv_bfloat16* Bsrc = (p == 1) ? Bl : Bh;
        const uint32_t sa = smb + (c % NSTG) * STGB;
        const uint32_t sb = sa + OPB;
#pragma unroll
        for (int i = 0; i < 4; i++) {
            cp16(sa + swz(rowS[i], sgI[i]),
                 Asrc + (size_t)(m0 + rowS[i]) * DD + koff + sgI[i] * 8);
            cp16(sb + swz(rowS[i], sgI[i]),
                 Bsrc + (size_t)(n0 + rowS[i]) * DD + koff + sgI[i] * 8);
        }
        asm volatile("cp.async.commit_group;" ::: "memory");
    };

    const int a_row = lane & 15;
    const int aseg = (lane >> 4);
    const int b_row = (lane & 7) + ((lane >> 4) << 3);
    const int bseg = (lane >> 3) & 1;

    load_chunk(0);
    load_chunk(1);

    for (int c = 0; c < NCHUNK; c++) {
        asm volatile("cp.async.wait_group 1;" ::: "memory");
        __syncthreads();
        if (c + 2 < NCHUNK) load_chunk(c + 2);
        else asm volatile("cp.async.commit_group;" ::: "memory");  // keep accounting

        const uint32_t sa = smb + (c % NSTG) * STGB;
        const uint32_t sb = sa + OPB;

#pragma unroll
        for (int ks = 0; ks < 4; ks++) {
            uint32_t a[2][4];
#pragma unroll
            for (int mt = 0; mt < 2; mt++) {
                const int r = wm + mt * 16 + a_row;
                ldsm4(a[mt][0], a[mt][1], a[mt][2], a[mt][3],
                      sa + swz(r, 2 * ks + aseg));
            }
            uint32_t b[8][2];
#pragma unroll
            for (int np = 0; np < 4; np++) {
                const int r = wn + np * 16 + b_row;
                ldsm4(b[2 * np][0], b[2 * np][1], b[2 * np + 1][0], b[2 * np + 1][1],
                      sb + swz(r, 2 * ks + bseg));
            }
#pragma unroll
            for (int mt = 0; mt < 2; mt++)
#pragma unroll
                for (int nt = 0; nt < 8; nt++)
                    mma_bf16(acc[mt][nt], a[mt][0], a[mt][1], a[mt][2], a[mt][3],
                             b[nt][0], b[nt][1]);
        }
    }
    __syncthreads();

    const int erow = lane >> 2;
    const int ecol = (lane & 3) * 2;

    if (OMODE == 3) {
        // Transposed fp16 split epilogue via smem staging (pad 132 floats).
        float* sT = (float*)dyn_smem;
        const int srow = tid >> 2;
        const int scol = (tid & 3) * 32;
#pragma unroll
        for (int hf = 0; hf < 2; hf++) {
            __syncthreads();
            if ((wid >> 2) == hf) {
#pragma unroll
                for (int mt = 0; mt < 2; mt++) {
                    const int m = wm + mt * 16 + erow;
#pragma unroll
                    for (int nt = 0; nt < 8; nt++) {
                        const int nl = nt * 8 + ecol;
                        sT[(nl + 0) * 132 + m] = acc[mt][nt][0];
                        sT[(nl + 1) * 132 + m] = acc[mt][nt][1];
                        sT[(nl + 0) * 132 + m + 8] = acc[mt][nt][2];
                        sT[(nl + 1) * 132 + m + 8] = acc[mt][nt][3];
                    }
                }
            }
            __syncthreads();
            const size_t n_glob = n0 + hf * 64 + srow;
            const float* sp = sT + srow * 132 + scol;
            __half* dh = Hh + n_glob * MM + m0 + scol;
            __half* dl = Hl + n_glob * MM + m0 + scol;
#pragma unroll
            for (int j = 0; j < 32; j += 2) {
                float f0 = sp[j], f1 = sp[j + 1];
                float h0 = __half2float(__float2half_rn(f0));
                float h1 = __half2float(__float2half_rn(f1));
                *(uint32_t*)(dh + j) = pack2h(f0, f1);
                *(uint32_t*)(dl + j) = pack2h(f0 - h0, f1 - h1);
            }
        }
        return;
    }

#pragma unroll
    for (int mt = 0; mt < 2; mt++) {
        const int row = m0 + wm + mt * 16 + erow;
#pragma unroll
        for (int nt = 0; nt < 8; nt++) {
            const int col = n0 + wn + nt * 8 + ecol;
            float v0 = acc[mt][nt][0], v1 = acc[mt][nt][1];
            float v2 = acc[mt][nt][2], v3 = acc[mt][nt][3];
            if (OMODE == 1) {
                v0 += bias[col]; v1 += bias[col + 1];
                v2 += bias[col]; v3 += bias[col + 1];
                float2 p0; p0.x = v0; p0.y = v1;
                float2 p1; p1.x = v2; p1.y = v3;
                *(float2*)&C[(size_t)row * DD + col] = p0;
                *(float2*)&C[(size_t)(row + 8) * DD + col] = p1;
            }
            if (OMODE == 2) {
                float h0 = __half2float(__float2half_rn(v0));
                float h1 = __half2float(__float2half_rn(v1));
                float h2 = __half2float(__float2half_rn(v2));
                float h3 = __half2float(__float2half_rn(v3));
                *(uint32_t*)&Hh[(size_t)row * DD + col] = pack2h(v0, v1);
                *(uint32_t*)&Hl[(size_t)row * DD + col] = pack2h(v0 - h0, v1 - h1);
                *(uint32_t*)&Hh[(size_t)(row + 8) * DD + col] = pack2h(v2, v3);
                *(uint32_t*)&Hl[(size_t)(row + 8) * DD + col] = pack2h(v2 - h2, v3 - h3);
            }
            if (OMODE == 4) {
                *(uint32_t*)&Hh[(size_t)row * DD + col] = pack2h(v0, v1);
                *(uint32_t*)&Hh[(size_t)(row + 8) * DD + col] = pack2h(v2, v3);
            }
        }
    }
}

// ---------------------------------------------------------------------------
// Prep kernels
// ---------------------------------------------------------------------------
__global__ __launch_bounds__(256)
void cvt_split_kernel(const float* __restrict__ in, __nv_bfloat16* __restrict__ hi,
                      __nv_bfloat16* __restrict__ lo, int n4) {
    int i = blockIdx.x * blockDim.x + threadIdx.x;
    if (i >= n4) return;
    float4 v = ((const float4*)in)[i];
    float h0 = __bfloat162float(__float2bfloat16(v.x));
    float h1 = __bfloat162float(__float2bfloat16(v.y));
    float h2 = __bfloat162float(__float2bfloat16(v.z));
    float h3 = __bfloat162float(__float2bfloat16(v.w));
    ((uint32_t*)hi)[2 * i + 0] = pack2(v.x, v.y);
    ((uint32_t*)hi)[2 * i + 1] = pack2(v.z, v.w);
    ((uint32_t*)lo)[2 * i + 0] = pack2(v.x - h0, v.y - h1);
    ((uint32_t*)lo)[2 * i + 1] = pack2(v.z - h2, v.w - h3);
}

__global__ __launch_bounds__(256)
void wsplit_t_all(const float* __restrict__ W0, const float* __restrict__ W1,
                  const float* __restrict__ W2, const float* __restrict__ W3,
                  __nv_bfloat16* __restrict__ Th, __nv_bfloat16* __restrict__ Tl) {
    __shared__ float t[32][33];
    const int z = blockIdx.z;
    const float* W = (z == 0) ? W0 : (z == 1) ? W1 : (z == 2) ? W2 : W3;
    __nv_bfloat16* th = Th + (size_t)z * DD * DD;
    __nv_bfloat16* tl = Tl + (size_t)z * DD * DD;
    const int bx = blockIdx.x * 32;
    const int by = blockIdx.y * 32;
    const int x = bx + threadIdx.x;
#pragma unroll
    for (int j = threadIdx.y; j < 32; j += 8)
        t[j][threadIdx.x] = W[(size_t)(by + j) * DD + x];
    __syncthreads();
    const int xo = by + threadIdx.x;
#pragma unroll
    for (int j = threadIdx.y; j < 32; j += 8) {
        float v = t[threadIdx.x][j];
        __nv_bfloat16 h = __float2bfloat16(v);
        th[(size_t)(bx + j) * DD + xo] = h;
        tl[(size_t)(bx + j) * DD + xo] = __float2bfloat16(v - __bfloat162float(h));
    }
}

// ---------------------------------------------------------------------------
// HMMA flash-attention, fp16 2-pass split:
//   QK = QhKh + QlKh (K fp16-hi only), PV = Ph(Vh+Vl) (P single fp16).
// Q tile 128, K/V tiles 64, double-buffered, SW128 smem (80KB, 2 CTA/SM),
// single barrier per tile. qt reversed (heavy blocks first).
// ---------------------------------------------------------------------------
#define QTB 16384                     // per Q tile (128 x 128B)
#define KVTB 8192                     // per K/V tile (64 x 128B)
#define KVSTGB (3 * KVTB)             // Kh + Vh + Vl = 24576 per stage
#define ATTN_SMEM_B (2 * QTB + 2 * KVSTGB)   // 81920

__global__ __launch_bounds__(256, 2)
void attn_mma(const __half* __restrict__ qh, const __half* __restrict__ ql,
              const __half* __restrict__ kh,
              const __half* __restrict__ vth, const __half* __restrict__ vtl,
              __nv_bfloat16* __restrict__ ch, __nv_bfloat16* __restrict__ cl) {
    extern __shared__ __align__(16) char attn_smem[];
    const uint32_t smb = smem_u32(attn_smem);

    const int tid = threadIdx.x;
    const int wid = tid >> 5;
    const int lane = tid & 31;
    const int qt = (SS / 128 - 1) - blockIdx.x;
    const int h = blockIdx.y;
    const int b = blockIdx.z;
    const int q0 = qt * 128;
    const int wm = wid * 16;
    const int g = lane >> 2;
    const int t_ = lane & 3;

    const size_t rowQ = (size_t)b * SS + q0;

    const int a_row = lane & 15;
    const int aseg = (lane >> 4);
    const int b_row = (lane & 7) + ((lane >> 4) << 3);
    const int bseg = (lane >> 3) & 1;

    // ---- load Q (hi+lo): 2048 segs of 16B ----
#pragma unroll
    for (int i = 0; i < 8; i++) {
        int gi = tid + 256 * i;
        int tile = gi >> 10;            // 0=Qh, 1=Ql
        int gg = gi & 1023;
        int row = gg >> 3, sg = gg & 7;
        const __half* src = (tile ? ql : qh) + (rowQ + row) * DD + h * HDIM + sg * 8;
        cp16(smb + tile * QTB + swz(row, sg), src);
    }

    auto load_kv = [&](int t, int s) {
        const size_t rowK = (size_t)b * SS + t * 64;
        const uint32_t base = smb + 2 * QTB + s * KVSTGB;
#pragma unroll
        for (int i = 0; i < 6; i++) {   // 1536 segs: Kh, Vh, Vl
            int gi = tid + 256 * i;
            int tile = gi >> 9;         // 0=Kh 1=Vh 2=Vl
            int gg = gi & 511;
            int row = gg >> 3, sg = gg & 7;
            const __half* src;
            if (tile == 0)      src = kh + (rowK + row) * DD + h * HDIM + sg * 8;
            else if (tile == 1) src = vth + (size_t)(h * HDIM + row) * MM + rowK + sg * 8;
            else                src = vtl + (size_t)(h * HDIM + row) * MM + rowK + sg * 8;
            cp16(base + tile * KVTB + swz(row, sg), src);
        }
        asm volatile("cp.async.commit_group;" ::: "memory");
    };

    const int ktiles = min(2 * qt + 3, SS / 64);

    load_kv(0, 0);   // Q copies ride in group 0

    float oacc[8][4];
    float m0 = -1e30f, m1 = -1e30f, l0 = 0.f, l1 = 0.f;
#pragma unroll
    for (int nt = 0; nt < 8; nt++)
#pragma unroll
        for (int e = 0; e < 4; e++) oacc[nt][e] = 0.f;

    for (int t = 0; t < ktiles; t++) {
        asm volatile("cp.async.wait_group 0;" ::: "memory");
        __syncthreads();
        if (t + 1 < ktiles) load_kv(t + 1, (t + 1) & 1);

        const int s = t & 1;
        const int k0 = t * 64;
        const bool skip = (k0 > q0 + 127) && (wid != 7);

        if (!skip) {
            const uint32_t sQh = smb;
            const uint32_t sQl = smb + QTB;
            const uint32_t sKh = smb + 2 * QTB + s * KVSTGB;
            const uint32_t sVh = sKh + KVTB;
            const uint32_t sVl = sKh + 2 * KVTB;

            float sacc[8][4];
#pragma unroll
            for (int nt = 0; nt < 8; nt++)
#pragma unroll
                for (int e = 0; e < 4; e++) sacc[nt][e] = 0.f;

            // ---- S = Qh K^T + Ql K^T (fused 2-pass) ----
#pragma unroll
            for (int ks = 0; ks < 4; ks++) {
                uint32_t aH0, aH1, aH2, aH3, aL0, aL1, aL2, aL3;
                ldsm4(aH0, aH1, aH2, aH3, sQh + swz(wm + a_row, 2 * ks + aseg));
                ldsm4(aL0, aL1, aL2, aL3, sQl + swz(wm + a_row, 2 * ks + aseg));
#pragma unroll
                for (int np = 0; np < 4; np++) {
                    uint32_t b0, b1, b2, b3;
                    ldsm4(b0, b1, b2, b3, sKh + swz(np * 16 + b_row, 2 * ks + bseg));
                    mma_f16(sacc[2 * np],     aH0, aH1, aH2, aH3, b0, b1);
                    mma_f16(sacc[2 * np + 1], aH0, aH1, aH2, aH3, b2, b3);
                    mma_f16(sacc[2 * np],     aL0, aL1, aL2, aL3, b0, b1);
                    mma_f16(sacc[2 * np + 1], aL0, aL1, aL2, aL3, b2, b3);
                }
            }

#pragma unroll
            for (int nt = 0; nt < 8; nt++)
#pragma unroll
                for (int e = 0; e < 4; e++) sacc[nt][e] *= 0.125f;

            const int qr0 = q0 + wm + g;
            if (k0 >= q0) {
#pragma unroll
                for (int nt = 0; nt < 8; nt++) {
                    const int c = k0 + nt * 8 + 2 * t_;
                    if (c     > qr0 + 1) sacc[nt][0] = -1e30f;
                    if (c + 1 > qr0 + 1) sacc[nt][1] = -1e30f;
                    if (c     > qr0 + 9) sacc[nt][2] = -1e30f;
                    if (c + 1 > qr0 + 9) sacc[nt][3] = -1e30f;
                }
            }

            float mx0 = -1e30f, mx1 = -1e30f;
#pragma unroll
            for (int nt = 0; nt < 8; nt++) {
                mx0 = fmaxf(mx0, fmaxf(sacc[nt][0], sacc[nt][1]));
                mx1 = fmaxf(mx1, fmaxf(sacc[nt][2], sacc[nt][3]));
            }
            mx0 = fmaxf(mx0, __shfl_xor_sync(0xffffffffu, mx0, 1));
            mx0 = fmaxf(mx0, __shfl_xor_sync(0xffffffffu, mx0, 2));
            mx1 = fmaxf(mx1, __shfl_xor_sync(0xffffffffu, mx1, 1));
            mx1 = fmaxf(mx1, __shfl_xor_sync(0xffffffffu, mx1, 2));

            const float mn0 = fmaxf(m0, mx0), mn1 = fmaxf(m1, mx1);
            const float cor0 = __expf(m0 - mn0), cor1 = __expf(m1 - mn1);
            m0 = mn0; m1 = mn1;

            float rs0 = 0.f, rs1 = 0.f;
#pragma unroll
            for (int nt = 0; nt < 8; nt++) {
                sacc[nt][0] = __expf(sacc[nt][0] - mn0); rs0 += sacc[nt][0];
                sacc[nt][1] = __expf(sacc[nt][1] - mn0); rs0 += sacc[nt][1];
                sacc[nt][2] = __expf(sacc[nt][2] - mn1); rs1 += sacc[nt][2];
                sacc[nt][3] = __expf(sacc[nt][3] - mn1); rs1 += sacc[nt][3];
            }
            rs0 += __shfl_xor_sync(0xffffffffu, rs0, 1);
            rs0 += __shfl_xor_sync(0xffffffffu, rs0, 2);
            rs1 += __shfl_xor_sync(0xffffffffu, rs1, 1);
            rs1 += __shfl_xor_sync(0xffffffffu, rs1, 2);
            l0 = l0 * cor0 + rs0;
            l1 = l1 * cor1 + rs1;

#pragma unroll
            for (int nt = 0; nt < 8; nt++) {
                oacc[nt][0] *= cor0; oacc[nt][1] *= cor0;
                oacc[nt][2] *= cor1; oacc[nt][3] *= cor1;
            }

            // ---- O += P (Vh + Vl), P single fp16 ----
#pragma unroll
            for (int ks = 0; ks < 4; ks++) {
                const float* P0 = sacc[2 * ks];
                const float* P1 = sacc[2 * ks + 1];
                uint32_t ah0 = pack2h(P0[0], P0[1]);
                uint32_t ah1 = pack2h(P0[2], P0[3]);
                uint32_t ah2 = pack2h(P1[0], P1[1]);
                uint32_t ah3 = pack2h(P1[2], P1[3]);
#pragma unroll
                for (int np = 0; np < 4; np++) {
                    uint32_t bh0, bh1, bh2, bh3, bl0, bl1, bl2, bl3;
                    ldsm4(bh0, bh1, bh2, bh3, sVh + swz(np * 16 + b_row, 2 * ks + bseg));
                    ldsm4(bl0, bl1, bl2, bl3, sVl + swz(np * 16 + b_row, 2 * ks + bseg));
                    mma_f16(oacc[2 * np],     ah0, ah1, ah2, ah3, bh0, bh1);
                    mma_f16(oacc[2 * np + 1], ah0, ah1, ah2, ah3, bh2, bh3);
                    mma_f16(oacc[2 * np],     ah0, ah1, ah2, ah3, bl0, bl1);
                    mma_f16(oacc[2 * np + 1], ah0, ah1, ah2, ah3, bl2, bl3);
                }
            }
        }
    }

    const float il0 = 1.0f / l0, il1 = 1.0f / l1;
    const size_t r0g = (size_t)b * SS + q0 + wm + g;
    const size_t r1g = r0g + 8;
#pragma unroll
    for (int nt = 0; nt < 8; nt++) {
        const int col = h * HDIM + nt * 8 + 2 * t_;
        float f0 = oacc[nt][0] * il0, f1 = oacc[nt][1] * il0;
        float f2 = oacc[nt][2] * il1, f3 = oacc[nt][3] * il1;
        float e0 = __bfloat162float(__float2bfloat16(f0));
        float e1 = __bfloat162float(__float2bfloat16(f1));
        float e2 = __bfloat162float(__float2bfloat16(f2));
        float e3 = __bfloat162float(__float2bfloat16(f3));
        *(uint32_t*)&ch[r0g * DD + col] = pack2(f0, f1);
        *(uint32_t*)&cl[r0g * DD + col] = pack2(f0 - e0, f1 - e1);
        *(uint32_t*)&ch[r1g * DD + col] = pack2(f2, f3);
        *(uint32_t*)&cl[r1g * DD + col] = pack2(f2 - e2, f3 - e3);
    }
}

// ---------------------------------------------------------------------------
// kernel_launch
// ---------------------------------------------------------------------------
extern "C" void kernel_launch(void* const* d_in, const int* in_sizes, int n_in,
                              void* d_out, int out_size) {
    (void)in_sizes; (void)n_in; (void)out_size;
    const float* x  = (const float*)d_in[0];
    const float* Wq = (const float*)d_in[1];
    const float* Wk = (const float*)d_in[2];
    const float* Wv = (const float*)d_in[3];
    const float* Wo = (const float*)d_in[4];
    const float* bo = (const float*)d_in[5];
    float* out = (float*)d_out;

    __nv_bfloat16 *xh, *xl, *ch, *cl, *wh, *wl;
    __half *qh, *ql, *kh, *vth, *vtl;
    cudaGetSymbolAddress((void**)&xh, g_xh);
    cudaGetSymbolAddress((void**)&xl, g_xl);
    cudaGetSymbolAddress((void**)&qh, g_qh);
    cudaGetSymbolAddress((void**)&ql, g_ql);
    cudaGetSymbolAddress((void**)&kh, g_kh);
    cudaGetSymbolAddress((void**)&vth, g_vth);
    cudaGetSymbolAddress((void**)&vtl, g_vtl);
    cudaGetSymbolAddress((void**)&ch, g_ch);
    cudaGetSymbolAddress((void**)&cl, g_cl);
    cudaGetSymbolAddress((void**)&wh, g_wh);
    cudaGetSymbolAddress((void**)&wl, g_wl);

    cudaFuncSetAttribute(attn_mma, cudaFuncAttributeMaxDynamicSharedMemorySize, ATTN_SMEM_B);
    cudaFuncSetAttribute(gemm_mma<1>, cudaFuncAttributeMaxDynamicSharedMemorySize, GEMM_SMEM);
    cudaFuncSetAttribute(gemm_mma<2>, cudaFuncAttributeMaxDynamicSharedMemorySize, GEMM_SMEM);
    cudaFuncSetAttribute(gemm_mma<3>, cudaFuncAttributeMaxDynamicSharedMemorySize, GEMM_SMEM);
    cudaFuncSetAttribute(gemm_mma<4>, cudaFuncAttributeMaxDynamicSharedMemorySize, GEMM_SMEM);

    // Prep
    const int n4 = MM * DD / 4;
    cvt_split_kernel<<<(n4 + 255) / 256, 256>>>(x, xh, xl, n4);
    dim3 tgrid(DD / 32, DD / 32, 4), tblk(32, 8);
    wsplit_t_all<<<tgrid, tblk>>>(Wq, Wk, Wv, Wo, wh, wl);

    // Projections: Q -> fp16 split; K -> fp16 hi; V -> transposed fp16 split
    dim3 ggrid(DD / 128, MM / 128);
    gemm_mma<2><<<ggrid, 256, GEMM_SMEM>>>(xh, xl, wh + 0 * DD * DD, wl + 0 * DD * DD,
                                           nullptr, nullptr, qh, ql);
    gemm_mma<4><<<ggrid, 256, GEMM_SMEM>>>(xh, xl, wh + 1 * DD * DD, wl + 1 * DD * DD,
                                           nullptr, nullptr, kh, nullptr);
    gemm_mma<3><<<ggrid, 256, GEMM_SMEM>>>(xh, xl, wh + 2 * DD * DD, wl + 2 * DD * DD,
                                           nullptr, nullptr, vth, vtl);

    // Attention (fp16 2-pass HMMA)
    dim3 agrid(SS / 128, HH, BB);
    attn_mma<<<agrid, 256, ATTN_SMEM_B>>>(qh, ql, kh, vth, vtl, ch, cl);

    // Output projection (+bias), bf16 3-pass
    gemm_mma<1><<<ggrid, 256, GEMM_SMEM>>>(ch, cl, wh + 3 * DD * DD, wl + 3 * DD * DD,
                                           bo, out, nullptr, nullptr);
}

// round 15
// speedup vs baseline: 1.4222x; 1.1899x over previous
#include <cuda_runtime.h>
#include <cuda_bf16.h>
#include <cuda_fp16.h>
#include <cstdint>

// Problem constants
#define BB 4
#define SS 2048
#define DD 1024
#define HH 16
#define HDIM 64
#define MM (BB * SS)   // 8192

// ---------------------------------------------------------------------------
// Static device scratch
// ---------------------------------------------------------------------------
__device__ __half g_xh[MM * DD];               // x fp16 hi
__device__ __half g_xl[MM * DD];               // x fp16 lo
__device__ __half g_qh[MM * DD];
__device__ __half g_ql[MM * DD];
__device__ __half g_kh[MM * DD];               // K hi only
__device__ __half g_vth[DD * MM];              // V^T hi: [DD][MM]
__device__ __half g_vtl[DD * MM];              // V^T lo
__device__ __nv_bfloat16 g_ch[MM * DD];        // ctx bf16 hi (out-proj input)
__device__ __nv_bfloat16 g_cl[MM * DD];        // ctx bf16 lo
__device__ __half g_wh16[3][DD * DD];          // Wq,Wk,Wv transposed fp16 hi
__device__ __nv_bfloat16 g_woh[DD * DD];       // Wo transposed bf16 hi
__device__ __nv_bfloat16 g_wol[DD * DD];       // Wo transposed bf16 lo

// ---------------------------------------------------------------------------
// PTX helpers
// ---------------------------------------------------------------------------
__device__ __forceinline__ uint32_t smem_u32(const void* p) {
    return (uint32_t)__cvta_generic_to_shared(p);
}

__device__ __forceinline__ void cp16(uint32_t dst, const void* src) {
    asm volatile("cp.async.cg.shared.global [%0], [%1], 16;" :: "r"(dst), "l"(src));
}

__device__ __forceinline__ void ldsm4(uint32_t& r0, uint32_t& r1, uint32_t& r2,
                                      uint32_t& r3, uint32_t addr) {
    asm volatile("ldmatrix.sync.aligned.m8n8.x4.shared.b16 {%0,%1,%2,%3}, [%4];"
                 : "=r"(r0), "=r"(r1), "=r"(r2), "=r"(r3) : "r"(addr));
}

__device__ __forceinline__ void mma_bf16(float c[4], uint32_t a0, uint32_t a1,
                                         uint32_t a2, uint32_t a3,
                                         uint32_t b0, uint32_t b1) {
    asm volatile(
        "mma.sync.aligned.m16n8k16.row.col.f32.bf16.bf16.f32 "
        "{%0,%1,%2,%3}, {%4,%5,%6,%7}, {%8,%9}, {%0,%1,%2,%3};"
        : "+f"(c[0]), "+f"(c[1]), "+f"(c[2]), "+f"(c[3])
        : "r"(a0), "r"(a1), "r"(a2), "r"(a3), "r"(b0), "r"(b1));
}

__device__ __forceinline__ void mma_f16(float c[4], uint32_t a0, uint32_t a1,
                                        uint32_t a2, uint32_t a3,
                                        uint32_t b0, uint32_t b1) {
    asm volatile(
        "mma.sync.aligned.m16n8k16.row.col.f32.f16.f16.f32 "
        "{%0,%1,%2,%3}, {%4,%5,%6,%7}, {%8,%9}, {%0,%1,%2,%3};"
        : "+f"(c[0]), "+f"(c[1]), "+f"(c[2]), "+f"(c[3])
        : "r"(a0), "r"(a1), "r"(a2), "r"(a3), "r"(b0), "r"(b1));
}

template <typename T>
__device__ __forceinline__ void mma_op(float c[4], uint32_t a0, uint32_t a1,
                                       uint32_t a2, uint32_t a3,
                                       uint32_t b0, uint32_t b1);
template <>
__device__ __forceinline__ void mma_op<__half>(float c[4], uint32_t a0, uint32_t a1,
                                               uint32_t a2, uint32_t a3,
                                               uint32_t b0, uint32_t b1) {
    mma_f16(c, a0, a1, a2, a3, b0, b1);
}
template <>
__device__ __forceinline__ void mma_op<__nv_bfloat16>(float c[4], uint32_t a0, uint32_t a1,
                                                      uint32_t a2, uint32_t a3,
                                                      uint32_t b0, uint32_t b1) {
    mma_bf16(c, a0, a1, a2, a3, b0, b1);
}

// pack2(lo, hi): bf16x2, lo in bits[15:0]
__device__ __forceinline__ uint32_t pack2(float lo, float hi) {
    uint32_t r;
    asm("cvt.rn.bf16x2.f32 %0, %1, %2;" : "=r"(r) : "f"(hi), "f"(lo));
    return r;
}
// fp16x2 version
__device__ __forceinline__ uint32_t pack2h(float lo, float hi) {
    uint32_t r;
    asm("cvt.rn.f16x2.f32 %0, %1, %2;" : "=r"(r) : "f"(hi), "f"(lo));
    return r;
}

// SW128 swizzle for 128B rows
__device__ __forceinline__ uint32_t swz(int row, int sg) {
    return (uint32_t)(row * 128 + (((sg ^ row) & 7) << 4));
}

// ---------------------------------------------------------------------------
// Split HMMA GEMM: 128x128 tile, 8 warps, 3-stage pipeline, KC=64, SW128 smem,
// single barrier per iteration.
// PASSES=2 (fp16): C = Ah*Bh + Al*Bh      (Bl unused)
// PASSES=3 (bf16): C = Ah*Bh + Ah*Bl + Al*Bh
// OMODE: 1 = fp32 + bias, 2 = fp16 hi/lo split, 3 = transposed fp16 split,
//        4 = fp16 hi only.
// ---------------------------------------------------------------------------
#define KC 64
#define OPB 16384
#define STGB (2 * OPB)
#define NSTG 3
#define GEMM_SMEM (NSTG * STGB)      // 98304

template <int OMODE, int PASSES, typename T>
__global__ __launch_bounds__(256, 2)
void gemm_mma(const T* __restrict__ Ah, const T* __restrict__ Al,
              const T* __restrict__ Bh, const T* __restrict__ Bl,
              const float* __restrict__ bias, float* __restrict__ C,
              __half* __restrict__ Hh, __half* __restrict__ Hl) {
    constexpr int NCH = 16 * PASSES;
    extern __shared__ __align__(16) char dyn_smem[];
    const uint32_t smb = smem_u32(dyn_smem);

    const int tid = threadIdx.x;
    const int wid = tid >> 5;
    const int lane = tid & 31;
    const int wm = (wid & 3) * 32;
    const int wn = (wid >> 2) * 64;
    const int m0 = blockIdx.y * 128;
    const int n0 = blockIdx.x * 128;

    float acc[2][8][4];
#pragma unroll
    for (int i = 0; i < 2; i++)
#pragma unroll
        for (int j = 0; j < 8; j++)
#pragma unroll
            for (int t = 0; t < 4; t++) acc[i][j][t] = 0.f;

    int rowS[4], sgI[4];
#pragma unroll
    for (int i = 0; i < 4; i++) {
        int seg = tid + 256 * i;
        rowS[i] = seg >> 3;
        sgI[i] = seg & 7;
    }

    auto load_chunk = [&](int c) {
        const int p = c >> 4;
        const int koff = (c & 15) * KC;
        const T* Asrc;
        const T* Bsrc;
        if (PASSES == 2) {
            Asrc = p ? Al : Ah;            // pass 0: Ah*Bh, pass 1: Al*Bh
            Bsrc = Bh;
        } else {
            Asrc = (p < 2) ? Ah : Al;      // AhBh, AhBl, AlBh
            Bsrc = (p == 1) ? Bl : Bh;
        }
        const uint32_t sa = smb + (c % NSTG) * STGB;
        const uint32_t sb = sa + OPB;
#pragma unroll
        for (int i = 0; i < 4; i++) {
            cp16(sa + swz(rowS[i], sgI[i]),
                 Asrc + (size_t)(m0 + rowS[i]) * DD + koff + sgI[i] * 8);
            cp16(sb + swz(rowS[i], sgI[i]),
                 Bsrc + (size_t)(n0 + rowS[i]) * DD + koff + sgI[i] * 8);
        }
        asm volatile("cp.async.commit_group;" ::: "memory");
    };

    const int a_row = lane & 15;
    const int aseg = (lane >> 4);
    const int b_row = (lane & 7) + ((lane >> 4) << 3);
    const int bseg = (lane >> 3) & 1;

    load_chunk(0);
    load_chunk(1);

    for (int c = 0; c < NCH; c++) {
        asm volatile("cp.async.wait_group 1;" ::: "memory");
        __syncthreads();
        if (c + 2 < NCH) load_chunk(c + 2);
        else asm volatile("cp.async.commit_group;" ::: "memory");

        const uint32_t sa = smb + (c % NSTG) * STGB;
        const uint32_t sb = sa + OPB;

#pragma unroll
        for (int ks = 0; ks < 4; ks++) {
            uint32_t a[2][4];
#pragma unroll
            for (int mt = 0; mt < 2; mt++) {
                const int r = wm + mt * 16 + a_row;
                ldsm4(a[mt][0], a[mt][1], a[mt][2], a[mt][3],
                      sa + swz(r, 2 * ks + aseg));
            }
            uint32_t b[8][2];
#pragma unroll
            for (int np = 0; np < 4; np++) {
                const int r = wn + np * 16 + b_row;
                ldsm4(b[2 * np][0], b[2 * np][1], b[2 * np + 1][0], b[2 * np + 1][1],
                      sb + swz(r, 2 * ks + bseg));
            }
#pragma unroll
            for (int mt = 0; mt < 2; mt++)
#pragma unroll
                for (int nt = 0; nt < 8; nt++)
                    mma_op<T>(acc[mt][nt], a[mt][0], a[mt][1], a[mt][2], a[mt][3],
                              b[nt][0], b[nt][1]);
        }
    }
    __syncthreads();

    const int erow = lane >> 2;
    const int ecol = (lane & 3) * 2;

    if (OMODE == 3) {
        // Transposed fp16 split epilogue via smem staging (pad 132 floats).
        float* sT = (float*)dyn_smem;
        const int srow = tid >> 2;
        const int scol = (tid & 3) * 32;
#pragma unroll
        for (int hf = 0; hf < 2; hf++) {
            __syncthreads();
            if ((wid >> 2) == hf) {
#pragma unroll
                for (int mt = 0; mt < 2; mt++) {
                    const int m = wm + mt * 16 + erow;
#pragma unroll
                    for (int nt = 0; nt < 8; nt++) {
                        const int nl = nt * 8 + ecol;
                        sT[(nl + 0) * 132 + m] = acc[mt][nt][0];
                        sT[(nl + 1) * 132 + m] = acc[mt][nt][1];
                        sT[(nl + 0) * 132 + m + 8] = acc[mt][nt][2];
                        sT[(nl + 1) * 132 + m + 8] = acc[mt][nt][3];
                    }
                }
            }
            __syncthreads();
            const size_t n_glob = n0 + hf * 64 + srow;
            const float* sp = sT + srow * 132 + scol;
            __half* dh = Hh + n_glob * MM + m0 + scol;
            __half* dl = Hl + n_glob * MM + m0 + scol;
#pragma unroll
            for (int j = 0; j < 32; j += 2) {
                float f0 = sp[j], f1 = sp[j + 1];
                float h0 = __half2float(__float2half_rn(f0));
                float h1 = __half2float(__float2half_rn(f1));
                *(uint32_t*)(dh + j) = pack2h(f0, f1);
                *(uint32_t*)(dl + j) = pack2h(f0 - h0, f1 - h1);
            }
        }
        return;
    }

#pragma unroll
    for (int mt = 0; mt < 2; mt++) {
        const int row = m0 + wm + mt * 16 + erow;
#pragma unroll
        for (int nt = 0; nt < 8; nt++) {
            const int col = n0 + wn + nt * 8 + ecol;
            float v0 = acc[mt][nt][0], v1 = acc[mt][nt][1];
            float v2 = acc[mt][nt][2], v3 = acc[mt][nt][3];
            if (OMODE == 1) {
                v0 += bias[col]; v1 += bias[col + 1];
                v2 += bias[col]; v3 += bias[col + 1];
                float2 p0; p0.x = v0; p0.y = v1;
                float2 p1; p1.x = v2; p1.y = v3;
                *(float2*)&C[(size_t)row * DD + col] = p0;
                *(float2*)&C[(size_t)(row + 8) * DD + col] = p1;
            }
            if (OMODE == 2) {
                float h0 = __half2float(__float2half_rn(v0));
                float h1 = __half2float(__float2half_rn(v1));
                float h2 = __half2float(__float2half_rn(v2));
                float h3 = __half2float(__float2half_rn(v3));
                *(uint32_t*)&Hh[(size_t)row * DD + col] = pack2h(v0, v1);
                *(uint32_t*)&Hl[(size_t)row * DD + col] = pack2h(v0 - h0, v1 - h1);
                *(uint32_t*)&Hh[(size_t)(row + 8) * DD + col] = pack2h(v2, v3);
                *(uint32_t*)&Hl[(size_t)(row + 8) * DD + col] = pack2h(v2 - h2, v3 - h3);
            }
            if (OMODE == 4) {
                *(uint32_t*)&Hh[(size_t)row * DD + col] = pack2h(v0, v1);
                *(uint32_t*)&Hh[(size_t)(row + 8) * DD + col] = pack2h(v2, v3);
            }
        }
    }
}

// ---------------------------------------------------------------------------
// Prep kernels
// ---------------------------------------------------------------------------
// x fp32 -> fp16 hi/lo
__global__ __launch_bounds__(256)
void cvt_split_f16(const float* __restrict__ in, __half* __restrict__ hi,
                   __half* __restrict__ lo, int n4) {
    int i = blockIdx.x * blockDim.x + threadIdx.x;
    if (i >= n4) return;
    float4 v = ((const float4*)in)[i];
    float h0 = __half2float(__float2half_rn(v.x));
    float h1 = __half2float(__float2half_rn(v.y));
    float h2 = __half2float(__float2half_rn(v.z));
    float h3 = __half2float(__float2half_rn(v.w));
    ((uint32_t*)hi)[2 * i + 0] = pack2h(v.x, v.y);
    ((uint32_t*)hi)[2 * i + 1] = pack2h(v.z, v.w);
    ((uint32_t*)lo)[2 * i + 0] = pack2h(v.x - h0, v.y - h1);
    ((uint32_t*)lo)[2 * i + 1] = pack2h(v.z - h2, v.w - h3);
}

// W transpose+split: z<3 -> fp16 hi only (Wq,Wk,Wv); z=3 -> bf16 hi/lo (Wo).
__global__ __launch_bounds__(256)
void wsplit_t_all(const float* __restrict__ W0, const float* __restrict__ W1,
                  const float* __restrict__ W2, const float* __restrict__ W3,
                  __half* __restrict__ Wh16, __nv_bfloat16* __restrict__ Woh,
                  __nv_bfloat16* __restrict__ Wol) {
    __shared__ float t[32][33];
    const int z = blockIdx.z;
    const float* W = (z == 0) ? W0 : (z == 1) ? W1 : (z == 2) ? W2 : W3;
    const int bx = blockIdx.x * 32;
    const int by = blockIdx.y * 32;
    const int x = bx + threadIdx.x;
#pragma unroll
    for (int j = threadIdx.y; j < 32; j += 8)
        t[j][threadIdx.x] = W[(size_t)(by + j) * DD + x];
    __syncthreads();
    const int xo = by + threadIdx.x;
    if (z < 3) {
        __half* th = Wh16 + (size_t)z * DD * DD;
#pragma unroll
        for (int j = threadIdx.y; j < 32; j += 8)
            th[(size_t)(bx + j) * DD + xo] = __float2half_rn(t[threadIdx.x][j]);
    } else {
#pragma unroll
        for (int j = threadIdx.y; j < 32; j += 8) {
            float v = t[threadIdx.x][j];
            __nv_bfloat16 h = __float2bfloat16(v);
            Woh[(size_t)(bx + j) * DD + xo] = h;
            Wol[(size_t)(bx + j) * DD + xo] = __float2bfloat16(v - __bfloat162float(h));
        }
    }
}

// ---------------------------------------------------------------------------
// HMMA flash-attention, fp16 2-pass split (unchanged from round 14).
// ---------------------------------------------------------------------------
#define QTB 16384
#define KVTB 8192
#define KVSTGB (3 * KVTB)
#define ATTN_SMEM_B (2 * QTB + 2 * KVSTGB)   // 81920

__global__ __launch_bounds__(256, 2)
void attn_mma(const __half* __restrict__ qh, const __half* __restrict__ ql,
              const __half* __restrict__ kh,
              const __half* __restrict__ vth, const __half* __restrict__ vtl,
              __nv_bfloat16* __restrict__ ch, __nv_bfloat16* __restrict__ cl) {
    extern __shared__ __align__(16) char attn_smem[];
    const uint32_t smb = smem_u32(attn_smem);

    const int tid = threadIdx.x;
    const int wid = tid >> 5;
    const int lane = tid & 31;
    const int qt = (SS / 128 - 1) - blockIdx.x;
    const int h = blockIdx.y;
    const int b = blockIdx.z;
    const int q0 = qt * 128;
    const int wm = wid * 16;
    const int g = lane >> 2;
    const int t_ = lane & 3;

    const size_t rowQ = (size_t)b * SS + q0;

    const int a_row = lane & 15;
    const int aseg = (lane >> 4);
    const int b_row = (lane & 7) + ((lane >> 4) << 3);
    const int bseg = (lane >> 3) & 1;

#pragma unroll
    for (int i = 0; i < 8; i++) {
        int gi = tid + 256 * i;
        int tile = gi >> 10;
        int gg = gi & 1023;
        int row = gg >> 3, sg = gg & 7;
        const __half* src = (tile ? ql : qh) + (rowQ + row) * DD + h * HDIM + sg * 8;
        cp16(smb + tile * QTB + swz(row, sg), src);
    }

    auto load_kv = [&](int t, int s) {
        const size_t rowK = (size_t)b * SS + t * 64;
        const uint32_t base = smb + 2 * QTB + s * KVSTGB;
#pragma unroll
        for (int i = 0; i < 6; i++) {
            int gi = tid + 256 * i;
            int tile = gi >> 9;
            int gg = gi & 511;
            int row = gg >> 3, sg = gg & 7;
            const __half* src;
            if (tile == 0)      src = kh + (rowK + row) * DD + h * HDIM + sg * 8;
            else if (tile == 1) src = vth + (size_t)(h * HDIM + row) * MM + rowK + sg * 8;
            else                src = vtl + (size_t)(h * HDIM + row) * MM + rowK + sg * 8;
            cp16(base + tile * KVTB + swz(row, sg), src);
        }
        asm volatile("cp.async.commit_group;" ::: "memory");
    };

    const int ktiles = min(2 * qt + 3, SS / 64);

    load_kv(0, 0);

    float oacc[8][4];
    float m0 = -1e30f, m1 = -1e30f, l0 = 0.f, l1 = 0.f;
#pragma unroll
    for (int nt = 0; nt < 8; nt++)
#pragma unroll
        for (int e = 0; e < 4; e++) oacc[nt][e] = 0.f;

    for (int t = 0; t < ktiles; t++) {
        asm volatile("cp.async.wait_group 0;" ::: "memory");
        __syncthreads();
        if (t + 1 < ktiles) load_kv(t + 1, (t + 1) & 1);

        const int s = t & 1;
        const int k0 = t * 64;
        const bool skip = (k0 > q0 + 127) && (wid != 7);

        if (!skip) {
            const uint32_t sQh = smb;
            const uint32_t sQl = smb + QTB;
            const uint32_t sKh = smb + 2 * QTB + s * KVSTGB;
            const uint32_t sVh = sKh + KVTB;
            const uint32_t sVl = sKh + 2 * KVTB;

            float sacc[8][4];
#pragma unroll
            for (int nt = 0; nt < 8; nt++)
#pragma unroll
                for (int e = 0; e < 4; e++) sacc[nt][e] = 0.f;

#pragma unroll
            for (int ks = 0; ks < 4; ks++) {
                uint32_t aH0, aH1, aH2, aH3, aL0, aL1, aL2, aL3;
                ldsm4(aH0, aH1, aH2, aH3, sQh + swz(wm + a_row, 2 * ks + aseg));
                ldsm4(aL0, aL1, aL2, aL3, sQl + swz(wm + a_row, 2 * ks + aseg));
#pragma unroll
                for (int np = 0; np < 4; np++) {
                    uint32_t b0, b1, b2, b3;
                    ldsm4(b0, b1, b2, b3, sKh + swz(np * 16 + b_row, 2 * ks + bseg));
                    mma_f16(sacc[2 * np],     aH0, aH1, aH2, aH3, b0, b1);
                    mma_f16(sacc[2 * np + 1], aH0, aH1, aH2, aH3, b2, b3);
                    mma_f16(sacc[2 * np],     aL0, aL1, aL2, aL3, b0, b1);
                    mma_f16(sacc[2 * np + 1], aL0, aL1, aL2, aL3, b2, b3);
                }
            }

#pragma unroll
            for (int nt = 0; nt < 8; nt++)
#pragma unroll
                for (int e = 0; e < 4; e++) sacc[nt][e] *= 0.125f;

            const int qr0 = q0 + wm + g;
            if (k0 >= q0) {
#pragma unroll
                for (int nt = 0; nt < 8; nt++) {
                    const int c = k0 + nt * 8 + 2 * t_;
                    if (c     > qr0 + 1) sacc[nt][0] = -1e30f;
                    if (c + 1 > qr0 + 1) sacc[nt][1] = -1e30f;
                    if (c     > qr0 + 9) sacc[nt][2] = -1e30f;
                    if (c + 1 > qr0 + 9) sacc[nt][3] = -1e30f;
                }
            }

            float mx0 = -1e30f, mx1 = -1e30f;
#pragma unroll
            for (int nt = 0; nt < 8; nt++) {
                mx0 = fmaxf(mx0, fmaxf(sacc[nt][0], sacc[nt][1]));
                mx1 = fmaxf(mx1, fmaxf(sacc[nt][2], sacc[nt][3]));
            }
            mx0 = fmaxf(mx0, __shfl_xor_sync(0xffffffffu, mx0, 1));
            mx0 = fmaxf(mx0, __shfl_xor_sync(0xffffffffu, mx0, 2));
            mx1 = fmaxf(mx1, __shfl_xor_sync(0xffffffffu, mx1, 1));
            mx1 = fmaxf(mx1, __shfl_xor_sync(0xffffffffu, mx1, 2));

            const float mn0 = fmaxf(m0, mx0), mn1 = fmaxf(m1, mx1);
            const float cor0 = __expf(m0 - mn0), cor1 = __expf(m1 - mn1);
            m0 = mn0; m1 = mn1;

            float rs0 = 0.f, rs1 = 0.f;
#pragma unroll
            for (int nt = 0; nt < 8; nt++) {
                sacc[nt][0] = __expf(sacc[nt][0] - mn0); rs0 += sacc[nt][0];
                sacc[nt][1] = __expf(sacc[nt][1] - mn0); rs0 += sacc[nt][1];
                sacc[nt][2] = __expf(sacc[nt][2] - mn1); rs1 += sacc[nt][2];
                sacc[nt][3] = __expf(sacc[nt][3] - mn1); rs1 += sacc[nt][3];
            }
            rs0 += __shfl_xor_sync(0xffffffffu, rs0, 1);
            rs0 += __shfl_xor_sync(0xffffffffu, rs0, 2);
            rs1 += __shfl_xor_sync(0xffffffffu, rs1, 1);
            rs1 += __shfl_xor_sync(0xffffffffu, rs1, 2);
            l0 = l0 * cor0 + rs0;
            l1 = l1 * cor1 + rs1;

#pragma unroll
            for (int nt = 0; nt < 8; nt++) {
                oacc[nt][0] *= cor0; oacc[nt][1] *= cor0;
                oacc[nt][2] *= cor1; oacc[nt][3] *= cor1;
            }

#pragma unroll
            for (int ks = 0; ks < 4; ks++) {
                const float* P0 = sacc[2 * ks];
                const float* P1 = sacc[2 * ks + 1];
                uint32_t ah0 = pack2h(P0[0], P0[1]);
                uint32_t ah1 = pack2h(P0[2], P0[3]);
                uint32_t ah2 = pack2h(P1[0], P1[1]);
                uint32_t ah3 = pack2h(P1[2], P1[3]);
#pragma unroll
                for (int np = 0; np < 4; np++) {
                    uint32_t bh0, bh1, bh2, bh3, bl0, bl1, bl2, bl3;
                    ldsm4(bh0, bh1, bh2, bh3, sVh + swz(np * 16 + b_row, 2 * ks + bseg));
                    ldsm4(bl0, bl1, bl2, bl3, sVl + swz(np * 16 + b_row, 2 * ks + bseg));
                    mma_f16(oacc[2 * np],     ah0, ah1, ah2, ah3, bh0, bh1);
                    mma_f16(oacc[2 * np + 1], ah0, ah1, ah2, ah3, bh2, bh3);
                    mma_f16(oacc[2 * np],     ah0, ah1, ah2, ah3, bl0, bl1);
                    mma_f16(oacc[2 * np + 1], ah0, ah1, ah2, ah3, bl2, bl3);
                }
            }
        }
    }

    const float il0 = 1.0f / l0, il1 = 1.0f / l1;
    const size_t r0g = (size_t)b * SS + q0 + wm + g;
    const size_t r1g = r0g + 8;
#pragma unroll
    for (int nt = 0; nt < 8; nt++) {
        const int col = h * HDIM + nt * 8 + 2 * t_;
        float f0 = oacc[nt][0] * il0, f1 = oacc[nt][1] * il0;
        float f2 = oacc[nt][2] * il1, f3 = oacc[nt][3] * il1;
        float e0 = __bfloat162float(__float2bfloat16(f0));
        float e1 = __bfloat162float(__float2bfloat16(f1));
        float e2 = __bfloat162float(__float2bfloat16(f2));
        float e3 = __bfloat162float(__float2bfloat16(f3));
        *(uint32_t*)&ch[r0g * DD + col] = pack2(f0, f1);
        *(uint32_t*)&cl[r0g * DD + col] = pack2(f0 - e0, f1 - e1);
        *(uint32_t*)&ch[r1g * DD + col] = pack2(f2, f3);
        *(uint32_t*)&cl[r1g * DD + col] = pack2(f2 - e2, f3 - e3);
    }
}

// ---------------------------------------------------------------------------
// kernel_launch
// ---------------------------------------------------------------------------
extern "C" void kernel_launch(void* const* d_in, const int* in_sizes, int n_in,
                              void* d_out, int out_size) {
    (void)in_sizes; (void)n_in; (void)out_size;
    const float* x  = (const float*)d_in[0];
    const float* Wq = (const float*)d_in[1];
    const float* Wk = (const float*)d_in[2];
    const float* Wv = (const float*)d_in[3];
    const float* Wo = (const float*)d_in[4];
    const float* bo = (const float*)d_in[5];
    float* out = (float*)d_out;

    __half *xh, *xl, *qh, *ql, *kh, *vth, *vtl, *wh16;
    __nv_bfloat16 *ch, *cl, *woh, *wol;
    cudaGetSymbolAddress((void**)&xh, g_xh);
    cudaGetSymbolAddress((void**)&xl, g_xl);
    cudaGetSymbolAddress((void**)&qh, g_qh);
    cudaGetSymbolAddress((void**)&ql, g_ql);
    cudaGetSymbolAddress((void**)&kh, g_kh);
    cudaGetSymbolAddress((void**)&vth, g_vth);
    cudaGetSymbolAddress((void**)&vtl, g_vtl);
    cudaGetSymbolAddress((void**)&ch, g_ch);
    cudaGetSymbolAddress((void**)&cl, g_cl);
    cudaGetSymbolAddress((void**)&wh16, g_wh16);
    cudaGetSymbolAddress((void**)&woh, g_woh);
    cudaGetSymbolAddress((void**)&wol, g_wol);

    cudaFuncSetAttribute(attn_mma, cudaFuncAttributeMaxDynamicSharedMemorySize, ATTN_SMEM_B);
    cudaFuncSetAttribute((gemm_mma<2, 2, __half>), cudaFuncAttributeMaxDynamicSharedMemorySize, GEMM_SMEM);
    cudaFuncSetAttribute((gemm_mma<4, 2, __half>), cudaFuncAttributeMaxDynamicSharedMemorySize, GEMM_SMEM);
    cudaFuncSetAttribute((gemm_mma<3, 2, __half>), cudaFuncAttributeMaxDynamicSharedMemorySize, GEMM_SMEM);
    cudaFuncSetAttribute((gemm_mma<1, 3, __nv_bfloat16>), cudaFuncAttributeMaxDynamicSharedMemorySize, GEMM_SMEM);

    // Prep
    const int n4 = MM * DD / 4;
    cvt_split_f16<<<(n4 + 255) / 256, 256>>>(x, xh, xl, n4);
    dim3 tgrid(DD / 32, DD / 32, 4), tblk(32, 8);
    wsplit_t_all<<<tgrid, tblk>>>(Wq, Wk, Wv, Wo, wh16, woh, wol);

    // Projections: fp16 2-pass (Q split, K hi, V transposed split)
    dim3 ggrid(DD / 128, MM / 128);
    gemm_mma<2, 2, __half><<<ggrid, 256, GEMM_SMEM>>>(
        xh, xl, wh16 + 0 * (size_t)DD * DD, nullptr, nullptr, nullptr, qh, ql);
    gemm_mma<4, 2, __half><<<ggrid, 256, GEMM_SMEM>>>(
        xh, xl, wh16 + 1 * (size_t)DD * DD, nullptr, nullptr, nullptr, kh, nullptr);
    gemm_mma<3, 2, __half><<<ggrid, 256, GEMM_SMEM>>>(
        xh, xl, wh16 + 2 * (size_t)DD * DD, nullptr, nullptr, nullptr, vth, vtl);

    // Attention (fp16 2-pass HMMA)
    dim3 agrid(SS / 128, HH, BB);
    attn_mma<<<agrid, 256, ATTN_SMEM_B>>>(qh, ql, kh, vth, vtl, ch, cl);

    // Output projection (+bias): bf16 3-pass (accuracy hedge)
    gemm_mma<1, 3, __nv_bfloat16><<<ggrid, 256, GEMM_SMEM>>>(
        ch, cl, woh, wol, bo, out, nullptr, nullptr);
}

// round 16
// speedup vs baseline: 1.5811x; 1.1117x over previous
#include <cuda_runtime.h>
#include <cuda_bf16.h>
#include <cuda_fp16.h>
#include <cstdint>

// Problem constants
#define BB 4
#define SS 2048
#define DD 1024
#define HH 16
#define HDIM 64
#define MM (BB * SS)   // 8192

// ---------------------------------------------------------------------------
// Static device scratch
// ---------------------------------------------------------------------------
__device__ __half g_xh[MM * DD];               // x fp16 hi
__device__ __half g_xl[MM * DD];               // x fp16 lo
__device__ __half g_qh[MM * DD];
__device__ __half g_ql[MM * DD];
__device__ __half g_kh[MM * DD];               // K hi only
__device__ __half g_vth[DD * MM];              // V^T hi: [DD][MM]
__device__ __half g_vtl[DD * MM];              // V^T lo
__device__ __half g_ch[MM * DD];               // ctx fp16 hi
__device__ __half g_cl[MM * DD];               // ctx fp16 lo
__device__ __half g_wh16[4][DD * DD];          // Wq,Wk,Wv,Wo transposed fp16 hi

// ---------------------------------------------------------------------------
// PTX helpers
// ---------------------------------------------------------------------------
__device__ __forceinline__ uint32_t smem_u32(const void* p) {
    return (uint32_t)__cvta_generic_to_shared(p);
}

__device__ __forceinline__ void cp16(uint32_t dst, const void* src) {
    asm volatile("cp.async.cg.shared.global [%0], [%1], 16;" :: "r"(dst), "l"(src));
}

__device__ __forceinline__ void ldsm4(uint32_t& r0, uint32_t& r1, uint32_t& r2,
                                      uint32_t& r3, uint32_t addr) {
    asm volatile("ldmatrix.sync.aligned.m8n8.x4.shared.b16 {%0,%1,%2,%3}, [%4];"
                 : "=r"(r0), "=r"(r1), "=r"(r2), "=r"(r3) : "r"(addr));
}

__device__ __forceinline__ void mma_f16(float c[4], uint32_t a0, uint32_t a1,
                                        uint32_t a2, uint32_t a3,
                                        uint32_t b0, uint32_t b1) {
    asm volatile(
        "mma.sync.aligned.m16n8k16.row.col.f32.f16.f16.f32 "
        "{%0,%1,%2,%3}, {%4,%5,%6,%7}, {%8,%9}, {%0,%1,%2,%3};"
        : "+f"(c[0]), "+f"(c[1]), "+f"(c[2]), "+f"(c[3])
        : "r"(a0), "r"(a1), "r"(a2), "r"(a3), "r"(b0), "r"(b1));
}

// fp16x2 pack: lo in bits[15:0], hi in bits[31:16]
__device__ __forceinline__ uint32_t pack2h(float lo, float hi) {
    uint32_t r;
    asm("cvt.rn.f16x2.f32 %0, %1, %2;" : "=r"(r) : "f"(hi), "f"(lo));
    return r;
}

// SW128 swizzle for 128B rows
__device__ __forceinline__ uint32_t swz(int row, int sg) {
    return (uint32_t)(row * 128 + (((sg ^ row) & 7) << 4));
}

// ---------------------------------------------------------------------------
// Fused fp16 2-pass HMMA GEMM: C = (Ah + Al) * Bh, 128x128 tile, 8 warps.
// Each chunk (KC=64) stages Ah+Al+Bh (48KB); both passes issued per B fragment.
// 2-stage pipeline (96KB smem, 2 CTA/SM), single barrier per chunk, 16 chunks.
// OMODE: 1 = fp32 + bias, 2 = fp16 hi/lo split, 3 = transposed fp16 split,
//        4 = fp16 hi only.
// ---------------------------------------------------------------------------
#define KC 64
#define TILB 16384                    // bytes per tile (128 rows x 128B)
#define STGB (3 * TILB)               // Ah + Al + Bh = 49152
#define GEMM_SMEM (2 * STGB)          // 98304

template <int OMODE>
__global__ __launch_bounds__(256, 2)
void gemm_mma(const __half* __restrict__ Ah, const __half* __restrict__ Al,
              const __half* __restrict__ Bh,
              const float* __restrict__ bias, float* __restrict__ C,
              __half* __restrict__ Hh, __half* __restrict__ Hl) {
    extern __shared__ __align__(16) char dyn_smem[];
    const uint32_t smb = smem_u32(dyn_smem);

    const int tid = threadIdx.x;
    const int wid = tid >> 5;
    const int lane = tid & 31;
    const int wm = (wid & 3) * 32;
    const int wn = (wid >> 2) * 64;
    const int m0 = blockIdx.y * 128;
    const int n0 = blockIdx.x * 128;

    float acc[2][8][4];
#pragma unroll
    for (int i = 0; i < 2; i++)
#pragma unroll
        for (int j = 0; j < 8; j++)
#pragma unroll
            for (int t = 0; t < 4; t++) acc[i][j][t] = 0.f;

    auto load_chunk = [&](int c) {
        const int koff = c * KC;
        const uint32_t sa = smb + (c & 1) * STGB;
#pragma unroll
        for (int i = 0; i < 12; i++) {      // 3072 segs of 16B
            int gi = tid + 256 * i;
            int tile = gi >> 10;            // 0=Ah 1=Al 2=Bh
            int gg = gi & 1023;
            int row = gg >> 3, sg = gg & 7;
            const __half* src =
                (tile == 0) ? Ah + (size_t)(m0 + row) * DD + koff + sg * 8 :
                (tile == 1) ? Al + (size_t)(m0 + row) * DD + koff + sg * 8 :
                              Bh + (size_t)(n0 + row) * DD + koff + sg * 8;
            cp16(sa + tile * TILB + swz(row, sg), src);
        }
        asm volatile("cp.async.commit_group;" ::: "memory");
    };

    const int a_row = lane & 15;
    const int aseg = (lane >> 4);
    const int b_row = (lane & 7) + ((lane >> 4) << 3);
    const int bseg = (lane >> 3) & 1;

    load_chunk(0);

    for (int c = 0; c < 16; c++) {
        asm volatile("cp.async.wait_group 0;" ::: "memory");
        __syncthreads();
        if (c + 1 < 16) load_chunk(c + 1);

        const uint32_t sAh = smb + (c & 1) * STGB;
        const uint32_t sAl = sAh + TILB;
        const uint32_t sB = sAh + 2 * TILB;

#pragma unroll
        for (int ks = 0; ks < 4; ks++) {
            uint32_t ah[2][4], al[2][4];
#pragma unroll
            for (int mt = 0; mt < 2; mt++) {
                const int r = wm + mt * 16 + a_row;
                ldsm4(ah[mt][0], ah[mt][1], ah[mt][2], ah[mt][3],
                      sAh + swz(r, 2 * ks + aseg));
                ldsm4(al[mt][0], al[mt][1], al[mt][2], al[mt][3],
                      sAl + swz(r, 2 * ks + aseg));
            }
#pragma unroll
            for (int np = 0; np < 4; np++) {
                uint32_t b0, b1, b2, b3;
                ldsm4(b0, b1, b2, b3, sB + swz(wn + np * 16 + b_row, 2 * ks + bseg));
#pragma unroll
                for (int mt = 0; mt < 2; mt++) {
                    mma_f16(acc[mt][2 * np],     ah[mt][0], ah[mt][1], ah[mt][2], ah[mt][3], b0, b1);
                    mma_f16(acc[mt][2 * np + 1], ah[mt][0], ah[mt][1], ah[mt][2], ah[mt][3], b2, b3);
                    mma_f16(acc[mt][2 * np],     al[mt][0], al[mt][1], al[mt][2], al[mt][3], b0, b1);
                    mma_f16(acc[mt][2 * np + 1], al[mt][0], al[mt][1], al[mt][2], al[mt][3], b2, b3);
                }
            }
        }
    }
    __syncthreads();

    const int erow = lane >> 2;
    const int ecol = (lane & 3) * 2;

    if (OMODE == 3) {
        // Transposed fp16 split epilogue via smem staging (pad 132 floats).
        float* sT = (float*)dyn_smem;
        const int srow = tid >> 2;
        const int scol = (tid & 3) * 32;
#pragma unroll
        for (int hf = 0; hf < 2; hf++) {
            __syncthreads();
            if ((wid >> 2) == hf) {
#pragma unroll
                for (int mt = 0; mt < 2; mt++) {
                    const int m = wm + mt * 16 + erow;
#pragma unroll
                    for (int nt = 0; nt < 8; nt++) {
                        const int nl = nt * 8 + ecol;
                        sT[(nl + 0) * 132 + m] = acc[mt][nt][0];
                        sT[(nl + 1) * 132 + m] = acc[mt][nt][1];
                        sT[(nl + 0) * 132 + m + 8] = acc[mt][nt][2];
                        sT[(nl + 1) * 132 + m + 8] = acc[mt][nt][3];
                    }
                }
            }
            __syncthreads();
            const size_t n_glob = n0 + hf * 64 + srow;
            const float* sp = sT + srow * 132 + scol;
            __half* dh = Hh + n_glob * MM + m0 + scol;
            __half* dl = Hl + n_glob * MM + m0 + scol;
#pragma unroll
            for (int j = 0; j < 32; j += 2) {
                float f0 = sp[j], f1 = sp[j + 1];
                float h0 = __half2float(__float2half_rn(f0));
                float h1 = __half2float(__float2half_rn(f1));
                *(uint32_t*)(dh + j) = pack2h(f0, f1);
                *(uint32_t*)(dl + j) = pack2h(f0 - h0, f1 - h1);
            }
        }
        return;
    }

#pragma unroll
    for (int mt = 0; mt < 2; mt++) {
        const int row = m0 + wm + mt * 16 + erow;
#pragma unroll
        for (int nt = 0; nt < 8; nt++) {
            const int col = n0 + wn + nt * 8 + ecol;
            float v0 = acc[mt][nt][0], v1 = acc[mt][nt][1];
            float v2 = acc[mt][nt][2], v3 = acc[mt][nt][3];
            if (OMODE == 1) {
                v0 += bias[col]; v1 += bias[col + 1];
                v2 += bias[col]; v3 += bias[col + 1];
                float2 p0; p0.x = v0; p0.y = v1;
                float2 p1; p1.x = v2; p1.y = v3;
                *(float2*)&C[(size_t)row * DD + col] = p0;
                *(float2*)&C[(size_t)(row + 8) * DD + col] = p1;
            }
            if (OMODE == 2) {
                float h0 = __half2float(__float2half_rn(v0));
                float h1 = __half2float(__float2half_rn(v1));
                float h2 = __half2float(__float2half_rn(v2));
                float h3 = __half2float(__float2half_rn(v3));
                *(uint32_t*)&Hh[(size_t)row * DD + col] = pack2h(v0, v1);
                *(uint32_t*)&Hl[(size_t)row * DD + col] = pack2h(v0 - h0, v1 - h1);
                *(uint32_t*)&Hh[(size_t)(row + 8) * DD + col] = pack2h(v2, v3);
                *(uint32_t*)&Hl[(size_t)(row + 8) * DD + col] = pack2h(v2 - h2, v3 - h3);
            }
            if (OMODE == 4) {
                *(uint32_t*)&Hh[(size_t)row * DD + col] = pack2h(v0, v1);
                *(uint32_t*)&Hh[(size_t)(row + 8) * DD + col] = pack2h(v2, v3);
            }
        }
    }
}

// ---------------------------------------------------------------------------
// Prep kernels
// ---------------------------------------------------------------------------
__global__ __launch_bounds__(256)
void cvt_split_f16(const float* __restrict__ in, __half* __restrict__ hi,
                   __half* __restrict__ lo, int n4) {
    int i = blockIdx.x * blockDim.x + threadIdx.x;
    if (i >= n4) return;
    float4 v = ((const float4*)in)[i];
    float h0 = __half2float(__float2half_rn(v.x));
    float h1 = __half2float(__float2half_rn(v.y));
    float h2 = __half2float(__float2half_rn(v.z));
    float h3 = __half2float(__float2half_rn(v.w));
    ((uint32_t*)hi)[2 * i + 0] = pack2h(v.x, v.y);
    ((uint32_t*)hi)[2 * i + 1] = pack2h(v.z, v.w);
    ((uint32_t*)lo)[2 * i + 0] = pack2h(v.x - h0, v.y - h1);
    ((uint32_t*)lo)[2 * i + 1] = pack2h(v.z - h2, v.w - h3);
}

// All four W: transpose -> fp16 hi (z selects matrix).
__global__ __launch_bounds__(256)
void wsplit_t_all(const float* __restrict__ W0, const float* __restrict__ W1,
                  const float* __restrict__ W2, const float* __restrict__ W3,
                  __half* __restrict__ Wh16) {
    __shared__ float t[32][33];
    const int z = blockIdx.z;
    const float* W = (z == 0) ? W0 : (z == 1) ? W1 : (z == 2) ? W2 : W3;
    __half* th = Wh16 + (size_t)z * DD * DD;
    const int bx = blockIdx.x * 32;
    const int by = blockIdx.y * 32;
    const int x = bx + threadIdx.x;
#pragma unroll
    for (int j = threadIdx.y; j < 32; j += 8)
        t[j][threadIdx.x] = W[(size_t)(by + j) * DD + x];
    __syncthreads();
    const int xo = by + threadIdx.x;
#pragma unroll
    for (int j = threadIdx.y; j < 32; j += 8)
        th[(size_t)(bx + j) * DD + xo] = __float2half_rn(t[threadIdx.x][j]);
}

// ---------------------------------------------------------------------------
// HMMA flash-attention, fp16 2-pass split (round-14/15 design; ctx out fp16).
// ---------------------------------------------------------------------------
#define QTB 16384
#define KVTB 8192
#define KVSTGB (3 * KVTB)
#define ATTN_SMEM_B (2 * QTB + 2 * KVSTGB)   // 81920

__global__ __launch_bounds__(256, 2)
void attn_mma(const __half* __restrict__ qh, const __half* __restrict__ ql,
              const __half* __restrict__ kh,
              const __half* __restrict__ vth, const __half* __restrict__ vtl,
              __half* __restrict__ ch, __half* __restrict__ cl) {
    extern __shared__ __align__(16) char attn_smem[];
    const uint32_t smb = smem_u32(attn_smem);

    const int tid = threadIdx.x;
    const int wid = tid >> 5;
    const int lane = tid & 31;
    const int qt = (SS / 128 - 1) - blockIdx.x;
    const int h = blockIdx.y;
    const int b = blockIdx.z;
    const int q0 = qt * 128;
    const int wm = wid * 16;
    const int g = lane >> 2;
    const int t_ = lane & 3;

    const size_t rowQ = (size_t)b * SS + q0;

    const int a_row = lane & 15;
    const int aseg = (lane >> 4);
    const int b_row = (lane & 7) + ((lane >> 4) << 3);
    const int bseg = (lane >> 3) & 1;

#pragma unroll
    for (int i = 0; i < 8; i++) {
        int gi = tid + 256 * i;
        int tile = gi >> 10;
        int gg = gi & 1023;
        int row = gg >> 3, sg = gg & 7;
        const __half* src = (tile ? ql : qh) + (rowQ + row) * DD + h * HDIM + sg * 8;
        cp16(smb + tile * QTB + swz(row, sg), src);
    }

    auto load_kv = [&](int t, int s) {
        const size_t rowK = (size_t)b * SS + t * 64;
        const uint32_t base = smb + 2 * QTB + s * KVSTGB;
#pragma unroll
        for (int i = 0; i < 6; i++) {
            int gi = tid + 256 * i;
            int tile = gi >> 9;
            int gg = gi & 511;
            int row = gg >> 3, sg = gg & 7;
            const __half* src;
            if (tile == 0)      src = kh + (rowK + row) * DD + h * HDIM + sg * 8;
            else if (tile == 1) src = vth + (size_t)(h * HDIM + row) * MM + rowK + sg * 8;
            else                src = vtl + (size_t)(h * HDIM + row) * MM + rowK + sg * 8;
            cp16(base + tile * KVTB + swz(row, sg), src);
        }
        asm volatile("cp.async.commit_group;" ::: "memory");
    };

    const int ktiles = min(2 * qt + 3, SS / 64);

    load_kv(0, 0);

    float oacc[8][4];
    float m0 = -1e30f, m1 = -1e30f, l0 = 0.f, l1 = 0.f;
#pragma unroll
    for (int nt = 0; nt < 8; nt++)
#pragma unroll
        for (int e = 0; e < 4; e++) oacc[nt][e] = 0.f;

    for (int t = 0; t < ktiles; t++) {
        asm volatile("cp.async.wait_group 0;" ::: "memory");
        __syncthreads();
        if (t + 1 < ktiles) load_kv(t + 1, (t + 1) & 1);

        const int s = t & 1;
        const int k0 = t * 64;
        const bool skip = (k0 > q0 + 127) && (wid != 7);

        if (!skip) {
            const uint32_t sQh = smb;
            const uint32_t sQl = smb + QTB;
            const uint32_t sKh = smb + 2 * QTB + s * KVSTGB;
            const uint32_t sVh = sKh + KVTB;
            const uint32_t sVl = sKh + 2 * KVTB;

            float sacc[8][4];
#pragma unroll
            for (int nt = 0; nt < 8; nt++)
#pragma unroll
                for (int e = 0; e < 4; e++) sacc[nt][e] = 0.f;

#pragma unroll
            for (int ks = 0; ks < 4; ks++) {
                uint32_t aH0, aH1, aH2, aH3, aL0, aL1, aL2, aL3;
                ldsm4(aH0, aH1, aH2, aH3, sQh + swz(wm + a_row, 2 * ks + aseg));
                ldsm4(aL0, aL1, aL2, aL3, sQl + swz(wm + a_row, 2 * ks + aseg));
#pragma unroll
                for (int np = 0; np < 4; np++) {
                    uint32_t b0, b1, b2, b3;
                    ldsm4(b0, b1, b2, b3, sKh + swz(np * 16 + b_row, 2 * ks + bseg));
                    mma_f16(sacc[2 * np],     aH0, aH1, aH2, aH3, b0, b1);
                    mma_f16(sacc[2 * np + 1], aH0, aH1, aH2, aH3, b2, b3);
                    mma_f16(sacc[2 * np],     aL0, aL1, aL2, aL3, b0, b1);
                    mma_f16(sacc[2 * np + 1], aL0, aL1, aL2, aL3, b2, b3);
                }
            }

#pragma unroll
            for (int nt = 0; nt < 8; nt++)
#pragma unroll
                for (int e = 0; e < 4; e++) sacc[nt][e] *= 0.125f;

            const int qr0 = q0 + wm + g;
            if (k0 >= q0) {
#pragma unroll
                for (int nt = 0; nt < 8; nt++) {
                    const int c = k0 + nt * 8 + 2 * t_;
                    if (c     > qr0 + 1) sacc[nt][0] = -1e30f;
                    if (c + 1 > qr0 + 1) sacc[nt][1] = -1e30f;
                    if (c     > qr0 + 9) sacc[nt][2] = -1e30f;
                    if (c + 1 > qr0 + 9) sacc[nt][3] = -1e30f;
                }
            }

            float mx0 = -1e30f, mx1 = -1e30f;
#pragma unroll
            for (int nt = 0; nt < 8; nt++) {
                mx0 = fmaxf(mx0, fmaxf(sacc[nt][0], sacc[nt][1]));
                mx1 = fmaxf(mx1, fmaxf(sacc[nt][2], sacc[nt][3]));
            }
            mx0 = fmaxf(mx0, __shfl_xor_sync(0xffffffffu, mx0, 1));
            mx0 = fmaxf(mx0, __shfl_xor_sync(0xffffffffu, mx0, 2));
            mx1 = fmaxf(mx1, __shfl_xor_sync(0xffffffffu, mx1, 1));
            mx1 = fmaxf(mx1, __shfl_xor_sync(0xffffffffu, mx1, 2));

            const float mn0 = fmaxf(m0, mx0), mn1 = fmaxf(m1, mx1);
            const float cor0 = __expf(m0 - mn0), cor1 = __expf(m1 - mn1);
            m0 = mn0; m1 = mn1;

            float rs0 = 0.f, rs1 = 0.f;
#pragma unroll
            for (int nt = 0; nt < 8; nt++) {
                sacc[nt][0] = __expf(sacc[nt][0] - mn0); rs0 += sacc[nt][0];
                sacc[nt][1] = __expf(sacc[nt][1] - mn0); rs0 += sacc[nt][1];
                sacc[nt][2] = __expf(sacc[nt][2] - mn1); rs1 += sacc[nt][2];
                sacc[nt][3] = __expf(sacc[nt][3] - mn1); rs1 += sacc[nt][3];
            }
            rs0 += __shfl_xor_sync(0xffffffffu, rs0, 1);
            rs0 += __shfl_xor_sync(0xffffffffu, rs0, 2);
            rs1 += __shfl_xor_sync(0xffffffffu, rs1, 1);
            rs1 += __shfl_xor_sync(0xffffffffu, rs1, 2);
            l0 = l0 * cor0 + rs0;
            l1 = l1 * cor1 + rs1;

#pragma unroll
            for (int nt = 0; nt < 8; nt++) {
                oacc[nt][0] *= cor0; oacc[nt][1] *= cor0;
                oacc[nt][2] *= cor1; oacc[nt][3] *= cor1;
            }

#pragma unroll
            for (int ks = 0; ks < 4; ks++) {
                const float* P0 = sacc[2 * ks];
                const float* P1 = sacc[2 * ks + 1];
                uint32_t ah0 = pack2h(P0[0], P0[1]);
                uint32_t ah1 = pack2h(P0[2], P0[3]);
                uint32_t ah2 = pack2h(P1[0], P1[1]);
                uint32_t ah3 = pack2h(P1[2], P1[3]);
#pragma unroll
                for (int np = 0; np < 4; np++) {
                    uint32_t bh0, bh1, bh2, bh3, bl0, bl1, bl2, bl3;
                    ldsm4(bh0, bh1, bh2, bh3, sVh + swz(np * 16 + b_row, 2 * ks + bseg));
                    ldsm4(bl0, bl1, bl2, bl3, sVl + swz(np * 16 + b_row, 2 * ks + bseg));
                    mma_f16(oacc[2 * np],     ah0, ah1, ah2, ah3, bh0, bh1);
                    mma_f16(oacc[2 * np + 1], ah0, ah1, ah2, ah3, bh2, bh3);
                    mma_f16(oacc[2 * np],     ah0, ah1, ah2, ah3, bl0, bl1);
                    mma_f16(oacc[2 * np + 1], ah0, ah1, ah2, ah3, bl2, bl3);
                }
            }
        }
    }

    // ---- epilogue: normalize, split to fp16 hi/lo ctx ----
    const float il0 = 1.0f / l0, il1 = 1.0f / l1;
    const size_t r0g = (size_t)b * SS + q0 + wm + g;
    const size_t r1g = r0g + 8;
#pragma unroll
    for (int nt = 0; nt < 8; nt++) {
        const int col = h * HDIM + nt * 8 + 2 * t_;
        float f0 = oacc[nt][0] * il0, f1 = oacc[nt][1] * il0;
        float f2 = oacc[nt][2] * il1, f3 = oacc[nt][3] * il1;
        float e0 = __half2float(__float2half_rn(f0));
        float e1 = __half2float(__float2half_rn(f1));
        float e2 = __half2float(__float2half_rn(f2));
        float e3 = __half2float(__float2half_rn(f3));
        *(uint32_t*)&ch[r0g * DD + col] = pack2h(f0, f1);
        *(uint32_t*)&cl[r0g * DD + col] = pack2h(f0 - e0, f1 - e1);
        *(uint32_t*)&ch[r1g * DD + col] = pack2h(f2, f3);
        *(uint32_t*)&cl[r1g * DD + col] = pack2h(f2 - e2, f3 - e3);
    }
}

// ---------------------------------------------------------------------------
// kernel_launch
// ---------------------------------------------------------------------------
extern "C" void kernel_launch(void* const* d_in, const int* in_sizes, int n_in,
                              void* d_out, int out_size) {
    (void)in_sizes; (void)n_in; (void)out_size;
    const float* x  = (const float*)d_in[0];
    const float* Wq = (const float*)d_in[1];
    const float* Wk = (const float*)d_in[2];
    const float* Wv = (const float*)d_in[3];
    const float* Wo = (const float*)d_in[4];
    const float* bo = (const float*)d_in[5];
    float* out = (float*)d_out;

    __half *xh, *xl, *qh, *ql, *kh, *vth, *vtl, *ch, *cl, *wh16;
    cudaGetSymbolAddress((void**)&xh, g_xh);
    cudaGetSymbolAddress((void**)&xl, g_xl);
    cudaGetSymbolAddress((void**)&qh, g_qh);
    cudaGetSymbolAddress((void**)&ql, g_ql);
    cudaGetSymbolAddress((void**)&kh, g_kh);
    cudaGetSymbolAddress((void**)&vth, g_vth);
    cudaGetSymbolAddress((void**)&vtl, g_vtl);
    cudaGetSymbolAddress((void**)&ch, g_ch);
    cudaGetSymbolAddress((void**)&cl, g_cl);
    cudaGetSymbolAddress((void**)&wh16, g_wh16);

    cudaFuncSetAttribute(attn_mma, cudaFuncAttributeMaxDynamicSharedMemorySize, ATTN_SMEM_B);
    cudaFuncSetAttribute(gemm_mma<1>, cudaFuncAttributeMaxDynamicSharedMemorySize, GEMM_SMEM);
    cudaFuncSetAttribute(gemm_mma<2>, cudaFuncAttributeMaxDynamicSharedMemorySize, GEMM_SMEM);
    cudaFuncSetAttribute(gemm_mma<3>, cudaFuncAttributeMaxDynamicSharedMemorySize, GEMM_SMEM);
    cudaFuncSetAttribute(gemm_mma<4>, cudaFuncAttributeMaxDynamicSharedMemorySize, GEMM_SMEM);

    // Prep
    const int n4 = MM * DD / 4;
    cvt_split_f16<<<(n4 + 255) / 256, 256>>>(x, xh, xl, n4);
    dim3 tgrid(DD / 32, DD / 32, 4), tblk(32, 8);
    wsplit_t_all<<<tgrid, tblk>>>(Wq, Wk, Wv, Wo, wh16);

    // Projections: fused fp16 2-pass (Q split, K hi, V transposed split)
    dim3 ggrid(DD / 128, MM / 128);
    gemm_mma<2><<<ggrid, 256, GEMM_SMEM>>>(
        xh, xl, wh16 + 0 * (size_t)DD * DD, nullptr, nullptr, qh, ql);
    gemm_mma<4><<<ggrid, 256, GEMM_SMEM>>>(
        xh, xl, wh16 + 1 * (size_t)DD * DD, nullptr, nullptr, kh, nullptr);
    gemm_mma<3><<<ggrid, 256, GEMM_SMEM>>>(
        xh, xl, wh16 + 2 * (size_t)DD * DD, nullptr, nullptr, vth, vtl);

    // Attention (fp16 2-pass HMMA)
    dim3 agrid(SS / 128, HH, BB);
    attn_mma<<<agrid, 256, ATTN_SMEM_B>>>(qh, ql, kh, vth, vtl, ch, cl);

    // Output projection (+bias): fused fp16 2-pass
    gemm_mma<1><<<ggrid, 256, GEMM_SMEM>>>(
        ch, cl, wh16 + 3 * (size_t)DD * DD, bo, out, nullptr, nullptr);
}

// round 17
// speedup vs baseline: 1.7696x; 1.1192x over previous
#include <cuda_runtime.h>
#include <cuda_bf16.h>
#include <cuda_fp16.h>
#include <cstdint>

// Problem constants
#define BB 4
#define SS 2048
#define DD 1024
#define HH 16
#define HDIM 64
#define MM (BB * SS)   // 8192

// ---------------------------------------------------------------------------
// Static device scratch
// ---------------------------------------------------------------------------
__device__ __half g_xh[MM * DD];               // x fp16 hi
__device__ __half g_xl[MM * DD];               // x fp16 lo
__device__ __half g_qh[MM * DD];               // Q hi only (1-pass QK)
__device__ __half g_kh[MM * DD];               // K hi only
__device__ __half g_vth[DD * MM];              // V^T hi: [DD][MM]
__device__ __half g_vtl[DD * MM];              // V^T lo
__device__ __half g_ch[MM * DD];               // ctx fp16 hi
__device__ __half g_cl[MM * DD];               // ctx fp16 lo
__device__ __half g_wh16[4][DD * DD];          // Wq,Wk,Wv,Wo transposed fp16 hi

// ---------------------------------------------------------------------------
// PTX helpers
// ---------------------------------------------------------------------------
__device__ __forceinline__ uint32_t smem_u32(const void* p) {
    return (uint32_t)__cvta_generic_to_shared(p);
}

__device__ __forceinline__ void cp16(uint32_t dst, const void* src) {
    asm volatile("cp.async.cg.shared.global [%0], [%1], 16;" :: "r"(dst), "l"(src));
}

__device__ __forceinline__ void ldsm4(uint32_t& r0, uint32_t& r1, uint32_t& r2,
                                      uint32_t& r3, uint32_t addr) {
    asm volatile("ldmatrix.sync.aligned.m8n8.x4.shared.b16 {%0,%1,%2,%3}, [%4];"
                 : "=r"(r0), "=r"(r1), "=r"(r2), "=r"(r3) : "r"(addr));
}

__device__ __forceinline__ void mma_f16(float c[4], uint32_t a0, uint32_t a1,
                                        uint32_t a2, uint32_t a3,
                                        uint32_t b0, uint32_t b1) {
    asm volatile(
        "mma.sync.aligned.m16n8k16.row.col.f32.f16.f16.f32 "
        "{%0,%1,%2,%3}, {%4,%5,%6,%7}, {%8,%9}, {%0,%1,%2,%3};"
        : "+f"(c[0]), "+f"(c[1]), "+f"(c[2]), "+f"(c[3])
        : "r"(a0), "r"(a1), "r"(a2), "r"(a3), "r"(b0), "r"(b1));
}

// fp16x2 pack: lo in bits[15:0], hi in bits[31:16]
__device__ __forceinline__ uint32_t pack2h(float lo, float hi) {
    uint32_t r;
    asm("cvt.rn.f16x2.f32 %0, %1, %2;" : "=r"(r) : "f"(hi), "f"(lo));
    return r;
}

// SW128 swizzle for 128B rows
__device__ __forceinline__ uint32_t swz(int row, int sg) {
    return (uint32_t)(row * 128 + (((sg ^ row) & 7) << 4));
}

// ---------------------------------------------------------------------------
// Fused fp16 2-pass HMMA GEMM core: acc = (Ah + Al) * Bh over K=1024.
// 128x128 tile, 8 warps, 2-stage pipeline (96KB smem), 16 chunks of KC=64.
// ---------------------------------------------------------------------------
#define KC 64
#define TILB 16384                    // bytes per tile (128 rows x 128B)
#define STGB (3 * TILB)               // Ah + Al + Bh = 49152
#define GEMM_SMEM (2 * STGB)          // 98304

__device__ __forceinline__ void gemm_core(
    const __half* __restrict__ Ah, const __half* __restrict__ Al,
    const __half* __restrict__ Bh, uint32_t smb, int m0, int n0,
    int tid, int wid, int lane, float acc[2][8][4]) {
    const int wm = (wid & 3) * 32;
    const int wn = (wid >> 2) * 64;

    auto load_chunk = [&](int c) {
        const int koff = c * KC;
        const uint32_t sa = smb + (c & 1) * STGB;
#pragma unroll
        for (int i = 0; i < 12; i++) {
            int gi = tid + 256 * i;
            int tile = gi >> 10;            // 0=Ah 1=Al 2=Bh
            int gg = gi & 1023;
            int row = gg >> 3, sg = gg & 7;
            const __half* src =
                (tile == 0) ? Ah + (size_t)(m0 + row) * DD + koff + sg * 8 :
                (tile == 1) ? Al + (size_t)(m0 + row) * DD + koff + sg * 8 :
                              Bh + (size_t)(n0 + row) * DD + koff + sg * 8;
            cp16(sa + tile * TILB + swz(row, sg), src);
        }
        asm volatile("cp.async.commit_group;" ::: "memory");
    };

    const int a_row = lane & 15;
    const int aseg = (lane >> 4);
    const int b_row = (lane & 7) + ((lane >> 4) << 3);
    const int bseg = (lane >> 3) & 1;

    load_chunk(0);

    for (int c = 0; c < 16; c++) {
        asm volatile("cp.async.wait_group 0;" ::: "memory");
        __syncthreads();
        if (c + 1 < 16) load_chunk(c + 1);

        const uint32_t sAh = smb + (c & 1) * STGB;
        const uint32_t sAl = sAh + TILB;
        const uint32_t sB = sAh + 2 * TILB;

#pragma unroll
        for (int ks = 0; ks < 4; ks++) {
            uint32_t ah[2][4], al[2][4];
#pragma unroll
            for (int mt = 0; mt < 2; mt++) {
                const int r = wm + mt * 16 + a_row;
                ldsm4(ah[mt][0], ah[mt][1], ah[mt][2], ah[mt][3],
                      sAh + swz(r, 2 * ks + aseg));
                ldsm4(al[mt][0], al[mt][1], al[mt][2], al[mt][3],
                      sAl + swz(r, 2 * ks + aseg));
            }
#pragma unroll
            for (int np = 0; np < 4; np++) {
                uint32_t b0, b1, b2, b3;
                ldsm4(b0, b1, b2, b3, sB + swz(wn + np * 16 + b_row, 2 * ks + bseg));
#pragma unroll
                for (int mt = 0; mt < 2; mt++) {
                    mma_f16(acc[mt][2 * np],     ah[mt][0], ah[mt][1], ah[mt][2], ah[mt][3], b0, b1);
                    mma_f16(acc[mt][2 * np + 1], ah[mt][0], ah[mt][1], ah[mt][2], ah[mt][3], b2, b3);
                    mma_f16(acc[mt][2 * np],     al[mt][0], al[mt][1], al[mt][2], al[mt][3], b0, b1);
                    mma_f16(acc[mt][2 * np + 1], al[mt][0], al[mt][1], al[mt][2], al[mt][3], b2, b3);
                }
            }
        }
    }
    __syncthreads();
}

// Combined Q/K/V projection: grid.z selects weight + epilogue.
//   z=0 -> qh (fp16 hi), z=1 -> kh (fp16 hi), z=2 -> vth/vtl (transposed split)
__global__ __launch_bounds__(256, 2)
void qkv_gemm(const __half* __restrict__ xh, const __half* __restrict__ xl,
              const __half* __restrict__ wh16,
              __half* __restrict__ qh, __half* __restrict__ kh,
              __half* __restrict__ vth, __half* __restrict__ vtl) {
    extern __shared__ __align__(16) char dyn_smem[];
    const uint32_t smb = smem_u32(dyn_smem);
    const int tid = threadIdx.x;
    const int wid = tid >> 5;
    const int lane = tid & 31;
    const int m0 = blockIdx.y * 128;
    const int n0 = blockIdx.x * 128;
    const int z = blockIdx.z;

    float acc[2][8][4];
#pragma unroll
    for (int i = 0; i < 2; i++)
#pragma unroll
        for (int j = 0; j < 8; j++)
#pragma unroll
            for (int t = 0; t < 4; t++) acc[i][j][t] = 0.f;

    gemm_core(xh, xl, wh16 + (size_t)z * DD * DD, smb, m0, n0, tid, wid, lane, acc);

    const int wm = (wid & 3) * 32;
    const int wn = (wid >> 2) * 64;
    const int erow = lane >> 2;
    const int ecol = (lane & 3) * 2;

    if (z == 2) {
        // Transposed fp16 split epilogue via smem staging (pad 132 floats).
        float* sT = (float*)dyn_smem;
        const int srow = tid >> 2;
        const int scol = (tid & 3) * 32;
#pragma unroll
        for (int hf = 0; hf < 2; hf++) {
            __syncthreads();
            if ((wid >> 2) == hf) {
#pragma unroll
                for (int mt = 0; mt < 2; mt++) {
                    const int m = wm + mt * 16 + erow;
#pragma unroll
                    for (int nt = 0; nt < 8; nt++) {
                        const int nl = nt * 8 + ecol;
                        sT[(nl + 0) * 132 + m] = acc[mt][nt][0];
                        sT[(nl + 1) * 132 + m] = acc[mt][nt][1];
                        sT[(nl + 0) * 132 + m + 8] = acc[mt][nt][2];
                        sT[(nl + 1) * 132 + m + 8] = acc[mt][nt][3];
                    }
                }
            }
            __syncthreads();
            const size_t n_glob = n0 + hf * 64 + srow;
            const float* sp = sT + srow * 132 + scol;
            __half* dh = vth + n_glob * MM + m0 + scol;
            __half* dl = vtl + n_glob * MM + m0 + scol;
#pragma unroll
            for (int j = 0; j < 32; j += 2) {
                float f0 = sp[j], f1 = sp[j + 1];
                float h0 = __half2float(__float2half_rn(f0));
                float h1 = __half2float(__float2half_rn(f1));
                *(uint32_t*)(dh + j) = pack2h(f0, f1);
                *(uint32_t*)(dl + j) = pack2h(f0 - h0, f1 - h1);
            }
        }
        return;
    }

    __half* dst = z ? kh : qh;
#pragma unroll
    for (int mt = 0; mt < 2; mt++) {
        const int row = m0 + wm + mt * 16 + erow;
#pragma unroll
        for (int nt = 0; nt < 8; nt++) {
            const int col = n0 + wn + nt * 8 + ecol;
            *(uint32_t*)&dst[(size_t)row * DD + col] = pack2h(acc[mt][nt][0], acc[mt][nt][1]);
            *(uint32_t*)&dst[(size_t)(row + 8) * DD + col] = pack2h(acc[mt][nt][2], acc[mt][nt][3]);
        }
    }
}

// Output projection: fp32 + bias
__global__ __launch_bounds__(256, 2)
void out_gemm(const __half* __restrict__ ch, const __half* __restrict__ cl,
              const __half* __restrict__ woh, const float* __restrict__ bias,
              float* __restrict__ C) {
    extern __shared__ __align__(16) char dyn_smem[];
    const uint32_t smb = smem_u32(dyn_smem);
    const int tid = threadIdx.x;
    const int wid = tid >> 5;
    const int lane = tid & 31;
    const int m0 = blockIdx.y * 128;
    const int n0 = blockIdx.x * 128;

    float acc[2][8][4];
#pragma unroll
    for (int i = 0; i < 2; i++)
#pragma unroll
        for (int j = 0; j < 8; j++)
#pragma unroll
            for (int t = 0; t < 4; t++) acc[i][j][t] = 0.f;

    gemm_core(ch, cl, woh, smb, m0, n0, tid, wid, lane, acc);

    const int wm = (wid & 3) * 32;
    const int wn = (wid >> 2) * 64;
    const int erow = lane >> 2;
    const int ecol = (lane & 3) * 2;
#pragma unroll
    for (int mt = 0; mt < 2; mt++) {
        const int row = m0 + wm + mt * 16 + erow;
#pragma unroll
        for (int nt = 0; nt < 8; nt++) {
            const int col = n0 + wn + nt * 8 + ecol;
            float2 p0, p1;
            p0.x = acc[mt][nt][0] + bias[col];
            p0.y = acc[mt][nt][1] + bias[col + 1];
            p1.x = acc[mt][nt][2] + bias[col];
            p1.y = acc[mt][nt][3] + bias[col + 1];
            *(float2*)&C[(size_t)row * DD + col] = p0;
            *(float2*)&C[(size_t)(row + 8) * DD + col] = p1;
        }
    }
}

// ---------------------------------------------------------------------------
// Prep kernels
// ---------------------------------------------------------------------------
__global__ __launch_bounds__(256)
void cvt_split_f16(const float* __restrict__ in, __half* __restrict__ hi,
                   __half* __restrict__ lo, int n4) {
    int i = blockIdx.x * blockDim.x + threadIdx.x;
    if (i >= n4) return;
    float4 v = ((const float4*)in)[i];
    float h0 = __half2float(__float2half_rn(v.x));
    float h1 = __half2float(__float2half_rn(v.y));
    float h2 = __half2float(__float2half_rn(v.z));
    float h3 = __half2float(__float2half_rn(v.w));
    ((uint32_t*)hi)[2 * i + 0] = pack2h(v.x, v.y);
    ((uint32_t*)hi)[2 * i + 1] = pack2h(v.z, v.w);
    ((uint32_t*)lo)[2 * i + 0] = pack2h(v.x - h0, v.y - h1);
    ((uint32_t*)lo)[2 * i + 1] = pack2h(v.z - h2, v.w - h3);
}

// All four W: transpose -> fp16 hi (z selects matrix).
__global__ __launch_bounds__(256)
void wsplit_t_all(const float* __restrict__ W0, const float* __restrict__ W1,
                  const float* __restrict__ W2, const float* __restrict__ W3,
                  __half* __restrict__ Wh16) {
    __shared__ float t[32][33];
    const int z = blockIdx.z;
    const float* W = (z == 0) ? W0 : (z == 1) ? W1 : (z == 2) ? W2 : W3;
    __half* th = Wh16 + (size_t)z * DD * DD;
    const int bx = blockIdx.x * 32;
    const int by = blockIdx.y * 32;
    const int x = bx + threadIdx.x;
#pragma unroll
    for (int j = threadIdx.y; j < 32; j += 8)
        t[j][threadIdx.x] = W[(size_t)(by + j) * DD + x];
    __syncthreads();
    const int xo = by + threadIdx.x;
#pragma unroll
    for (int j = threadIdx.y; j < 32; j += 8)
        th[(size_t)(bx + j) * DD + xo] = __float2half_rn(t[threadIdx.x][j]);
}

// ---------------------------------------------------------------------------
// HMMA flash-attention: QK single-pass fp16 (Qh·Kh), PV 2-pass (P·(Vh+Vl)).
// Q tile 128, K/V tiles 64, double-buffered, SW128 smem (64KB), 2 CTA/SM.
// ---------------------------------------------------------------------------
#define QTB 16384
#define KVTB 8192
#define KVSTGB (3 * KVTB)
#define ATTN_SMEM_B (QTB + 2 * KVSTGB)   // 65536

__global__ __launch_bounds__(256, 2)
void attn_mma(const __half* __restrict__ qh, const __half* __restrict__ kh,
              const __half* __restrict__ vth, const __half* __restrict__ vtl,
              __half* __restrict__ ch, __half* __restrict__ cl) {
    extern __shared__ __align__(16) char attn_smem[];
    const uint32_t smb = smem_u32(attn_smem);

    const int tid = threadIdx.x;
    const int wid = tid >> 5;
    const int lane = tid & 31;
    const int qt = (SS / 128 - 1) - blockIdx.x;
    const int h = blockIdx.y;
    const int b = blockIdx.z;
    const int q0 = qt * 128;
    const int wm = wid * 16;
    const int g = lane >> 2;
    const int t_ = lane & 3;

    const size_t rowQ = (size_t)b * SS + q0;

    const int a_row = lane & 15;
    const int aseg = (lane >> 4);
    const int b_row = (lane & 7) + ((lane >> 4) << 3);
    const int bseg = (lane >> 3) & 1;

    // ---- load Q hi: 1024 segs of 16B ----
#pragma unroll
    for (int i = 0; i < 4; i++) {
        int gi = tid + 256 * i;
        int row = gi >> 3, sg = gi & 7;
        cp16(smb + swz(row, sg), qh + (rowQ + row) * DD + h * HDIM + sg * 8);
    }

    auto load_kv = [&](int t, int s) {
        const size_t rowK = (size_t)b * SS + t * 64;
        const uint32_t base = smb + QTB + s * KVSTGB;
#pragma unroll
        for (int i = 0; i < 6; i++) {
            int gi = tid + 256 * i;
            int tile = gi >> 9;
            int gg = gi & 511;
            int row = gg >> 3, sg = gg & 7;
            const __half* src;
            if (tile == 0)      src = kh + (rowK + row) * DD + h * HDIM + sg * 8;
            else if (tile == 1) src = vth + (size_t)(h * HDIM + row) * MM + rowK + sg * 8;
            else                src = vtl + (size_t)(h * HDIM + row) * MM + rowK + sg * 8;
            cp16(base + tile * KVTB + swz(row, sg), src);
        }
        asm volatile("cp.async.commit_group;" ::: "memory");
    };

    const int ktiles = min(2 * qt + 3, SS / 64);

    load_kv(0, 0);

    float oacc[8][4];
    float m0 = -1e30f, m1 = -1e30f, l0 = 0.f, l1 = 0.f;
#pragma unroll
    for (int nt = 0; nt < 8; nt++)
#pragma unroll
        for (int e = 0; e < 4; e++) oacc[nt][e] = 0.f;

    for (int t = 0; t < ktiles; t++) {
        asm volatile("cp.async.wait_group 0;" ::: "memory");
        __syncthreads();
        if (t + 1 < ktiles) load_kv(t + 1, (t + 1) & 1);

        const int s = t & 1;
        const int k0 = t * 64;
        const bool skip = (k0 > q0 + 127) && (wid != 7);

        if (!skip) {
            const uint32_t sQ = smb;
            const uint32_t sKh = smb + QTB + s * KVSTGB;
            const uint32_t sVh = sKh + KVTB;
            const uint32_t sVl = sKh + 2 * KVTB;

            float sacc[8][4];
#pragma unroll
            for (int nt = 0; nt < 8; nt++)
#pragma unroll
                for (int e = 0; e < 4; e++) sacc[nt][e] = 0.f;

            // ---- S = Qh Kh^T (single pass) ----
#pragma unroll
            for (int ks = 0; ks < 4; ks++) {
                uint32_t a0, a1, a2, a3;
                ldsm4(a0, a1, a2, a3, sQ + swz(wm + a_row, 2 * ks + aseg));
#pragma unroll
                for (int np = 0; np < 4; np++) {
                    uint32_t b0, b1, b2, b3;
                    ldsm4(b0, b1, b2, b3, sKh + swz(np * 16 + b_row, 2 * ks + bseg));
                    mma_f16(sacc[2 * np],     a0, a1, a2, a3, b0, b1);
                    mma_f16(sacc[2 * np + 1], a0, a1, a2, a3, b2, b3);
                }
            }

#pragma unroll
            for (int nt = 0; nt < 8; nt++)
#pragma unroll
                for (int e = 0; e < 4; e++) sacc[nt][e] *= 0.125f;

            const int qr0 = q0 + wm + g;
            if (k0 >= q0) {
#pragma unroll
                for (int nt = 0; nt < 8; nt++) {
                    const int c = k0 + nt * 8 + 2 * t_;
                    if (c     > qr0 + 1) sacc[nt][0] = -1e30f;
                    if (c + 1 > qr0 + 1) sacc[nt][1] = -1e30f;
                    if (c     > qr0 + 9) sacc[nt][2] = -1e30f;
                    if (c + 1 > qr0 + 9) sacc[nt][3] = -1e30f;
                }
            }

            float mx0 = -1e30f, mx1 = -1e30f;
#pragma unroll
            for (int nt = 0; nt < 8; nt++) {
                mx0 = fmaxf(mx0, fmaxf(sacc[nt][0], sacc[nt][1]));
                mx1 = fmaxf(mx1, fmaxf(sacc[nt][2], sacc[nt][3]));
            }
            mx0 = fmaxf(mx0, __shfl_xor_sync(0xffffffffu, mx0, 1));
            mx0 = fmaxf(mx0, __shfl_xor_sync(0xffffffffu, mx0, 2));
            mx1 = fmaxf(mx1, __shfl_xor_sync(0xffffffffu, mx1, 1));
            mx1 = fmaxf(mx1, __shfl_xor_sync(0xffffffffu, mx1, 2));

            const float mn0 = fmaxf(m0, mx0), mn1 = fmaxf(m1, mx1);
            const float cor0 = __expf(m0 - mn0), cor1 = __expf(m1 - mn1);
            m0 = mn0; m1 = mn1;

            float rs0 = 0.f, rs1 = 0.f;
#pragma unroll
            for (int nt = 0; nt < 8; nt++) {
                sacc[nt][0] = __expf(sacc[nt][0] - mn0); rs0 += sacc[nt][0];
                sacc[nt][1] = __expf(sacc[nt][1] - mn0); rs0 += sacc[nt][1];
                sacc[nt][2] = __expf(sacc[nt][2] - mn1); rs1 += sacc[nt][2];
                sacc[nt][3] = __expf(sacc[nt][3] - mn1); rs1 += sacc[nt][3];
            }
            rs0 += __shfl_xor_sync(0xffffffffu, rs0, 1);
            rs0 += __shfl_xor_sync(0xffffffffu, rs0, 2);
            rs1 += __shfl_xor_sync(0xffffffffu, rs1, 1);
            rs1 += __shfl_xor_sync(0xffffffffu, rs1, 2);
            l0 = l0 * cor0 + rs0;
            l1 = l1 * cor1 + rs1;

#pragma unroll
            for (int nt = 0; nt < 8; nt++) {
                oacc[nt][0] *= cor0; oacc[nt][1] *= cor0;
                oacc[nt][2] *= cor1; oacc[nt][3] *= cor1;
            }

            // ---- O += P (Vh + Vl), P single fp16 ----
#pragma unroll
            for (int ks = 0; ks < 4; ks++) {
                const float* P0 = sacc[2 * ks];
                const float* P1 = sacc[2 * ks + 1];
                uint32_t ah0 = pack2h(P0[0], P0[1]);
                uint32_t ah1 = pack2h(P0[2], P0[3]);
                uint32_t ah2 = pack2h(P1[0], P1[1]);
                uint32_t ah3 = pack2h(P1[2], P1[3]);
#pragma unroll
                for (int np = 0; np < 4; np++) {
                    uint32_t bh0, bh1, bh2, bh3, bl0, bl1, bl2, bl3;
                    ldsm4(bh0, bh1, bh2, bh3, sVh + swz(np * 16 + b_row, 2 * ks + bseg));
                    ldsm4(bl0, bl1, bl2, bl3, sVl + swz(np * 16 + b_row, 2 * ks + bseg));
                    mma_f16(oacc[2 * np],     ah0, ah1, ah2, ah3, bh0, bh1);
                    mma_f16(oacc[2 * np + 1], ah0, ah1, ah2, ah3, bh2, bh3);
                    mma_f16(oacc[2 * np],     ah0, ah1, ah2, ah3, bl0, bl1);
                    mma_f16(oacc[2 * np + 1], ah0, ah1, ah2, ah3, bl2, bl3);
                }
            }
        }
    }

    // ---- epilogue: normalize, split to fp16 hi/lo ctx ----
    const float il0 = 1.0f / l0, il1 = 1.0f / l1;
    const size_t r0g = (size_t)b * SS + q0 + wm + g;
    const size_t r1g = r0g + 8;
#pragma unroll
    for (int nt = 0; nt < 8; nt++) {
        const int col = h * HDIM + nt * 8 + 2 * t_;
        float f0 = oacc[nt][0] * il0, f1 = oacc[nt][1] * il0;
        float f2 = oacc[nt][2] * il1, f3 = oacc[nt][3] * il1;
        float e0 = __half2float(__float2half_rn(f0));
        float e1 = __half2float(__float2half_rn(f1));
        float e2 = __half2float(__float2half_rn(f2));
        float e3 = __half2float(__float2half_rn(f3));
        *(uint32_t*)&ch[r0g * DD + col] = pack2h(f0, f1);
        *(uint32_t*)&cl[r0g * DD + col] = pack2h(f0 - e0, f1 - e1);
        *(uint32_t*)&ch[r1g * DD + col] = pack2h(f2, f3);
        *(uint32_t*)&cl[r1g * DD + col] = pack2h(f2 - e2, f3 - e3);
    }
}

// ---------------------------------------------------------------------------
// kernel_launch
// ---------------------------------------------------------------------------
extern "C" void kernel_launch(void* const* d_in, const int* in_sizes, int n_in,
                              void* d_out, int out_size) {
    (void)in_sizes; (void)n_in; (void)out_size;
    const float* x  = (const float*)d_in[0];
    const float* Wq = (const float*)d_in[1];
    const float* Wk = (const float*)d_in[2];
    const float* Wv = (const float*)d_in[3];
    const float* Wo = (const float*)d_in[4];
    const float* bo = (const float*)d_in[5];
    float* out = (float*)d_out;

    __half *xh, *xl, *qh, *kh, *vth, *vtl, *ch, *cl, *wh16;
    cudaGetSymbolAddress((void**)&xh, g_xh);
    cudaGetSymbolAddress((void**)&xl, g_xl);
    cudaGetSymbolAddress((void**)&qh, g_qh);
    cudaGetSymbolAddress((void**)&kh, g_kh);
    cudaGetSymbolAddress((void**)&vth, g_vth);
    cudaGetSymbolAddress((void**)&vtl, g_vtl);
    cudaGetSymbolAddress((void**)&ch, g_ch);
    cudaGetSymbolAddress((void**)&cl, g_cl);
    cudaGetSymbolAddress((void**)&wh16, g_wh16);

    cudaFuncSetAttribute(attn_mma, cudaFuncAttributeMaxDynamicSharedMemorySize, ATTN_SMEM_B);
    cudaFuncSetAttribute(qkv_gemm, cudaFuncAttributeMaxDynamicSharedMemorySize, GEMM_SMEM);
    cudaFuncSetAttribute(out_gemm, cudaFuncAttributeMaxDynamicSharedMemorySize, GEMM_SMEM);

    // Prep
    const int n4 = MM * DD / 4;
    cvt_split_f16<<<(n4 + 255) / 256, 256>>>(x, xh, xl, n4);
    dim3 tgrid(DD / 32, DD / 32, 4), tblk(32, 8);
    wsplit_t_all<<<tgrid, tblk>>>(Wq, Wk, Wv, Wo, wh16);

    // Combined Q/K/V projections (one launch, z selects output)
    dim3 qkv_grid(DD / 128, MM / 128, 3);
    qkv_gemm<<<qkv_grid, 256, GEMM_SMEM>>>(xh, xl, wh16, qh, kh, vth, vtl);

    // Attention (QK 1-pass, PV 2-pass fp16)
    dim3 agrid(SS / 128, HH, BB);
    attn_mma<<<agrid, 256, ATTN_SMEM_B>>>(qh, kh, vth, vtl, ch, cl);

    // Output projection (+bias): fused fp16 2-pass
    dim3 ggrid(DD / 128, MM / 128);
    out_gemm<<<ggrid, 256, GEMM_SMEM>>>(ch, cl, wh16 + 3 * (size_t)DD * DD, bo, out);
}